// round 7
// baseline (speedup 1.0000x reference)
#include <cuda_runtime.h>
#include <cuda_bf16.h>
#include <cstdint>

#define B 32
#define H 32
#define D 128
#define R 512
#define S 4096
#define HID 4096
#define SCALE 0.08838834764831845f
#define NSPLIT 8
#define SB (S / NSPLIT)
#define SC 32
#define NCHUNK (SB / SC)

// ---------------- scratch ----------------
__device__ float g_q[B * HID];
__device__ float g_part[8 * B * HID];
__device__ float g_qa[B * H * R];
__device__ float g_ctx[B * H * R];
__device__ float g_attn[B * HID];
__device__ float g_ctxp[NSPLIT * B * H * R];
__device__ float g_m[NSPLIT * B * H];
__device__ float g_l[NSPLIT * B * H];

// ---------------- helpers ----------------
__device__ __forceinline__ uint32_t pack2(__nv_bfloat16 a, __nv_bfloat16 b) {
    return (uint32_t)__bfloat16_as_ushort(a) | ((uint32_t)__bfloat16_as_ushort(b) << 16);
}
__device__ __forceinline__ void split_store(float4 v, __nv_bfloat16* hp, __nv_bfloat16* lp) {
    __nv_bfloat16 h0 = __float2bfloat16(v.x), h1 = __float2bfloat16(v.y),
                  h2 = __float2bfloat16(v.z), h3 = __float2bfloat16(v.w);
    __nv_bfloat16 l0 = __float2bfloat16(v.x - __bfloat162float(h0));
    __nv_bfloat16 l1 = __float2bfloat16(v.y - __bfloat162float(h1));
    __nv_bfloat16 l2 = __float2bfloat16(v.z - __bfloat162float(h2));
    __nv_bfloat16 l3 = __float2bfloat16(v.w - __bfloat162float(h3));
    *reinterpret_cast<uint2*>(hp) = make_uint2(pack2(h0, h1), pack2(h2, h3));
    *reinterpret_cast<uint2*>(lp) = make_uint2(pack2(l0, l1), pack2(l2, l3));
}
__device__ __forceinline__ uint32_t saddr(const void* p) {
    return (uint32_t)__cvta_generic_to_shared(p);
}
__device__ __forceinline__ void ldsm4(uint32_t* r, const void* p) {
    asm volatile("ldmatrix.sync.aligned.m8n8.x4.shared.b16 {%0,%1,%2,%3},[%4];\n"
                 : "=r"(r[0]), "=r"(r[1]), "=r"(r[2]), "=r"(r[3]) : "r"(saddr(p)));
}
__device__ __forceinline__ void ldsm4t(uint32_t* r, const void* p) {
    asm volatile("ldmatrix.sync.aligned.m8n8.x4.trans.shared.b16 {%0,%1,%2,%3},[%4];\n"
                 : "=r"(r[0]), "=r"(r[1]), "=r"(r[2]), "=r"(r[3]) : "r"(saddr(p)));
}
__device__ __forceinline__ void mma16816(float* c, const uint32_t* a, uint32_t b0, uint32_t b1) {
    asm volatile(
        "mma.sync.aligned.m16n8k16.row.col.f32.bf16.bf16.f32 "
        "{%0,%1,%2,%3},{%4,%5,%6,%7},{%8,%9},{%0,%1,%2,%3};\n"
        : "+f"(c[0]), "+f"(c[1]), "+f"(c[2]), "+f"(c[3])
        : "r"(a[0]), "r"(a[1]), "r"(a[2]), "r"(a[3]), "r"(b0), "r"(b1));
}

// ---------------- bf16 hi/lo GEMM-NT, split-K 8, double-buffered smem
#define GA 2560
#define GW 10240
#define G_A0H 0
#define G_A0L (GA)
#define G_A1H (2*GA)
#define G_A1L (3*GA)
#define G_W0H (4*GA)
#define G_W0L (4*GA + GW)
#define G_W1H (4*GA + 2*GW)
#define G_W1L (4*GA + 3*GW)
#define SMEM_GEMM (4*GA + 4*GW)

__global__ void __launch_bounds__(256) gemm_bf_k(const float* __restrict__ A,
                                                 const float* __restrict__ W) {
    extern __shared__ char gsm[];
    const int n0 = blockIdx.x * 128;
    const int ks = blockIdx.y;
    const int tid = threadIdx.x;
    const int warp = tid >> 5, lane = tid & 31;
    const int g = lane >> 2, t = lane & 3;
    float c[2][2][4] = {};

    const int ar = tid >> 3, ac = (tid & 7) * 4;
    {
        int k0 = ks * 512;
        float4 va = *reinterpret_cast<const float4*>(A + ar * HID + k0 + ac);
        split_store(va, (__nv_bfloat16*)(gsm + G_A0H) + ar * 40 + ac,
                        (__nv_bfloat16*)(gsm + G_A0L) + ar * 40 + ac);
#pragma unroll
        for (int it = 0; it < 4; it++) {
            int i = it * 256 + tid;
            int r = i >> 3, cc = (i & 7) * 4;
            float4 v = *reinterpret_cast<const float4*>(W + (size_t)(n0 + r) * HID + k0 + cc);
            split_store(v, (__nv_bfloat16*)(gsm + G_W0H) + r * 40 + cc,
                           (__nv_bfloat16*)(gsm + G_W0L) + r * 40 + cc);
        }
    }
    __syncthreads();

    for (int it16 = 0; it16 < 16; it16++) {
        const char* curA_h = gsm + ((it16 & 1) ? G_A1H : G_A0H);
        const char* curA_l = gsm + ((it16 & 1) ? G_A1L : G_A0L);
        const char* curW_h = gsm + ((it16 & 1) ? G_W1H : G_W0H);
        const char* curW_l = gsm + ((it16 & 1) ? G_W1L : G_W0L);
        char* nxtA_h = gsm + ((it16 & 1) ? G_A0H : G_A1H);
        char* nxtA_l = gsm + ((it16 & 1) ? G_A0L : G_A1L);
        char* nxtW_h = gsm + ((it16 & 1) ? G_W0H : G_W1H);
        char* nxtW_l = gsm + ((it16 & 1) ? G_W0L : G_W1L);
        bool pf = (it16 + 1) < 16;
        float4 va, vw[4];
        if (pf) {
            int k0 = ks * 512 + (it16 + 1) * 32;
            va = *reinterpret_cast<const float4*>(A + ar * HID + k0 + ac);
#pragma unroll
            for (int itw = 0; itw < 4; itw++) {
                int i = itw * 256 + tid;
                vw[itw] = *reinterpret_cast<const float4*>(
                    W + (size_t)(n0 + (i >> 3)) * HID + k0 + ((i & 7) * 4));
            }
        }
#pragma unroll
        for (int kk = 0; kk < 2; kk++) {
            uint32_t ah[2][4], al[2][4];
#pragma unroll
            for (int mi = 0; mi < 2; mi++) {
                ldsm4(ah[mi], (const __nv_bfloat16*)curA_h + (mi * 16 + (lane & 15)) * 40 + kk * 16 + (lane >> 4) * 8);
                ldsm4(al[mi], (const __nv_bfloat16*)curA_l + (mi * 16 + (lane & 15)) * 40 + kk * 16 + (lane >> 4) * 8);
            }
            int brow = warp * 16 + ((lane >> 4) << 3) + (lane & 7);
            int bcol = kk * 16 + (((lane >> 3) & 1) << 3);
            uint32_t bh[4], bl[4];
            ldsm4(bh, (const __nv_bfloat16*)curW_h + brow * 40 + bcol);
            ldsm4(bl, (const __nv_bfloat16*)curW_l + brow * 40 + bcol);
#pragma unroll
            for (int nf = 0; nf < 2; nf++)
#pragma unroll
                for (int mi = 0; mi < 2; mi++) {
                    mma16816(c[mi][nf], ah[mi], bh[nf * 2], bh[nf * 2 + 1]);
                    mma16816(c[mi][nf], ah[mi], bl[nf * 2], bl[nf * 2 + 1]);
                    mma16816(c[mi][nf], al[mi], bh[nf * 2], bh[nf * 2 + 1]);
                }
        }
        if (pf) {
            split_store(va, (__nv_bfloat16*)nxtA_h + ar * 40 + ac,
                            (__nv_bfloat16*)nxtA_l + ar * 40 + ac);
#pragma unroll
            for (int itw = 0; itw < 4; itw++) {
                int i = itw * 256 + tid;
                int r = i >> 3, cc = (i & 7) * 4;
                split_store(vw[itw], (__nv_bfloat16*)nxtW_h + r * 40 + cc,
                                     (__nv_bfloat16*)nxtW_l + r * 40 + cc);
            }
        }
        __syncthreads();
    }
#pragma unroll
    for (int mi = 0; mi < 2; mi++)
#pragma unroll
        for (int nf = 0; nf < 2; nf++) {
            int row = mi * 16 + g;
            int col = n0 + warp * 16 + nf * 8 + 2 * t;
            float* o = g_part + ks * (B * HID) + (size_t)row * HID + col;
            *reinterpret_cast<float2*>(o) = make_float2(c[mi][nf][0], c[mi][nf][1]);
            *reinterpret_cast<float2*>(o + 8 * HID) = make_float2(c[mi][nf][2], c[mi][nf][3]);
        }
}

// ---------------- reduces
__global__ void reduce8_k(float* __restrict__ dst, const float* __restrict__ bias) {
    int i = blockIdx.x * 256 + threadIdx.x;
    float v = 0.f;
#pragma unroll
    for (int s = 0; s < 8; s++) v += g_part[s * 131072 + i];
    if (bias) v += bias[i & (HID - 1)];
    dst[i] = v;
}
__global__ void reduce4_k(float* __restrict__ dst, const float* __restrict__ bias) {
    int i = blockIdx.x * 256 + threadIdx.x;
    float v = g_part[i] + g_part[131072 + i] + g_part[2 * 131072 + i] + g_part[3 * 131072 + i];
    if (bias) v += bias[i & (HID - 1)];
    dst[i] = v;
}

// ---------------- q_absorbed
__global__ void qabsorb_k(const float* __restrict__ w_kc) {
    const int h = blockIdx.y;
    const int r0 = blockIdx.x * 128;
    __shared__ float As[32][33];
    __shared__ float Bs[32][132];
    const int tid = threadIdx.x;
    const int ty = tid / 32, tx = tid % 32;
    float acc[4][4] = {};
    for (int d0 = 0; d0 < 128; d0 += 32) {
        {
            int r = tid / 8, c = (tid % 8) * 4;
            float4 v = *reinterpret_cast<const float4*>(g_q + r * HID + h * D + d0 + c);
            As[r][c] = v.x; As[r][c + 1] = v.y; As[r][c + 2] = v.z; As[r][c + 3] = v.w;
        }
#pragma unroll
        for (int it = 0; it < 4; it++) {
            int i = tid + it * 256;
            int rr = i / 32, c = (i % 32) * 4;
            float4 v = *reinterpret_cast<const float4*>(w_kc + (size_t)(h * D + d0 + rr) * R + r0 + c);
            *reinterpret_cast<float4*>(&Bs[rr][c]) = v;
        }
        __syncthreads();
#pragma unroll
        for (int dd = 0; dd < 32; dd++) {
            float4 bv = *reinterpret_cast<float4*>(&Bs[dd][tx * 4]);
            float bb[4] = {bv.x, bv.y, bv.z, bv.w};
#pragma unroll
            for (int i = 0; i < 4; i++) {
                float a = As[ty * 4 + i][dd];
#pragma unroll
                for (int j = 0; j < 4; j++) acc[i][j] += a * bb[j];
            }
        }
        __syncthreads();
    }
#pragma unroll
    for (int i = 0; i < 4; i++)
#pragma unroll
        for (int j = 0; j < 4; j++)
            g_qa[((ty * 4 + i) * H + h) * R + r0 + tx * 4 + j] = acc[i][j];
}

// ---------------- fused flash MLA: 512 threads, pipelined PV(i-1) || QK(i), 3 syncs/chunk ----------------
#define AST 520
#define PST 40
#define SRST 34
#define OFF_AH 0
#define OFF_AL 33280
#define OFF_V0H 66560
#define OFF_V0L 99840
#define OFF_V1H 133120
#define OFF_V1L 166400
#define OFF_PH 199680
#define OFF_PL 202240
#define OFF_SRED 204800
#define OFF_WMAX 217856
#define OFF_WSUM 218112
#define OFF_MROW 218368
#define OFF_LROW 218496
#define SMEM_FMLA 218624

__global__ void __launch_bounds__(512, 1) fmla_k(const float* __restrict__ ckv) {
    extern __shared__ char smbuf[];
    __nv_bfloat16* Ah = reinterpret_cast<__nv_bfloat16*>(smbuf + OFF_AH);
    __nv_bfloat16* Al = reinterpret_cast<__nv_bfloat16*>(smbuf + OFF_AL);
    __nv_bfloat16* Ph = reinterpret_cast<__nv_bfloat16*>(smbuf + OFF_PH);
    __nv_bfloat16* Pl = reinterpret_cast<__nv_bfloat16*>(smbuf + OFF_PL);
    float* Sred = reinterpret_cast<float*>(smbuf + OFF_SRED);
    float* wmax = reinterpret_cast<float*>(smbuf + OFF_WMAX);
    float* wsum = reinterpret_cast<float*>(smbuf + OFF_WSUM);
    float* mrow = reinterpret_cast<float*>(smbuf + OFF_MROW);
    float* lrow = reinterpret_cast<float*>(smbuf + OFF_LROW);

    const int sp = blockIdx.x, b = blockIdx.y;
    const int tid = threadIdx.x;
    const int warp = tid >> 5, lane = tid & 31;
    const int g = lane >> 2, t = lane & 3;
    const int kw = warp >> 2;
    const int mw = (warp >> 1) & 1;
    const int nw = warp & 1;

    // prologue: A and V(0)
#pragma unroll
    for (int it = 0; it < 8; it++) {
        int i = it * 512 + tid;
        int row = i >> 7, cc = (i & 127) * 4;
        float4 v = *reinterpret_cast<const float4*>(g_qa + (size_t)(b * H + row) * R + cc);
        split_store(v, &Ah[row * AST + cc], &Al[row * AST + cc]);
    }
    {
        const float4* src4 = reinterpret_cast<const float4*>(ckv + ((size_t)b * S + sp * SB) * R);
        __nv_bfloat16* Vh = reinterpret_cast<__nv_bfloat16*>(smbuf + OFF_V0H);
        __nv_bfloat16* Vl = reinterpret_cast<__nv_bfloat16*>(smbuf + OFF_V0L);
#pragma unroll
        for (int it = 0; it < 8; it++) {
            int i = it * 512 + tid;
            int row = i >> 7, cc = (i & 127) * 4;
            split_store(src4[i], &Vh[row * AST + cc], &Vl[row * AST + cc]);
        }
    }
    if (tid < 32) { mrow[tid] = -3e38f; lrow[tid] = 0.f; }
    __syncthreads();

    float cv[2][4][4] = {};

    for (int ii = 0; ii < NCHUNK; ii++) {
        __nv_bfloat16* Vqh = reinterpret_cast<__nv_bfloat16*>(smbuf + ((ii & 1) ? OFF_V1H : OFF_V0H));
        __nv_bfloat16* Vql = reinterpret_cast<__nv_bfloat16*>(smbuf + ((ii & 1) ? OFF_V1L : OFF_V0L));
        __nv_bfloat16* Vph = reinterpret_cast<__nv_bfloat16*>(smbuf + ((ii & 1) ? OFF_V0H : OFF_V1H));
        __nv_bfloat16* Vpl = reinterpret_cast<__nv_bfloat16*>(smbuf + ((ii & 1) ? OFF_V0L : OFF_V1L));
        const bool pf = (ii + 1) < NCHUNK;

        // running m/l update for chunk ii-1 (off critical path)
        if (tid < 32 && ii > 0) {
            float mo = mrow[tid];
            float cm = fmaxf(wmax[tid], wmax[32 + tid]);
            float mn = fmaxf(mo, cm);
            float a = __expf(mo - mn);
            lrow[tid] = lrow[tid] * a + wsum[tid] + wsum[32 + tid];
            mrow[tid] = mn;
        }

        const float4* src4 = reinterpret_cast<const float4*>(
            ckv + ((size_t)b * S + sp * SB + (ii + 1) * SC) * R);
        float4 pva[4], pvb[4];
        if (pf) {
#pragma unroll
            for (int j = 0; j < 4; j++) pva[j] = src4[j * 512 + tid];
        }

        // ---- PV for chunk ii-1 (uses Vp, Ph/Pl) ----
        if (ii > 0) {
#pragma unroll
            for (int kk = 0; kk < 2; kk++) {
                int k0 = kk * 16;
                uint32_t ph[2][4], pl[2][4];
#pragma unroll
                for (int mi = 0; mi < 2; mi++) {
                    ldsm4(ph[mi], &Ph[(mi * 16 + (lane & 15)) * PST + k0 + (lane >> 4) * 8]);
                    ldsm4(pl[mi], &Pl[(mi * 16 + (lane & 15)) * PST + k0 + (lane >> 4) * 8]);
                }
#pragma unroll
                for (int j2 = 0; j2 < 2; j2++) {
                    int vrow = k0 + (lane & 7) + (((lane >> 3) & 1) << 3);
                    int vcol = warp * 32 + j2 * 16 + (lane >> 4) * 8;
                    uint32_t vh[4], vl[4];
                    ldsm4t(vh, &Vph[vrow * AST + vcol]);
                    ldsm4t(vl, &Vpl[vrow * AST + vcol]);
#pragma unroll
                    for (int half = 0; half < 2; half++)
#pragma unroll
                        for (int mi = 0; mi < 2; mi++) {
                            float* cc = cv[mi][j2 * 2 + half];
                            mma16816(cc, ph[mi], vh[half * 2], vh[half * 2 + 1]);
                            mma16816(cc, ph[mi], vl[half * 2], vl[half * 2 + 1]);
                            mma16816(cc, pl[mi], vh[half * 2], vh[half * 2 + 1]);
                        }
                }
            }
        }

        // ---- QK for chunk ii ----
        float cq[2][4] = {};
#pragma unroll
        for (int kk = 0; kk < 8; kk++) {
            int k0 = kw * 128 + kk * 16;
            uint32_t ah[4], al[4];
            ldsm4(ah, &Ah[(mw * 16 + (lane & 15)) * AST + k0 + (lane >> 4) * 8]);
            ldsm4(al, &Al[(mw * 16 + (lane & 15)) * AST + k0 + (lane >> 4) * 8]);
            int brow = nw * 16 + ((lane >> 4) << 3) + (lane & 7);
            int bcol = k0 + (((lane >> 3) & 1) << 3);
            uint32_t bh[4], bl[4];
            ldsm4(bh, &Vqh[brow * AST + bcol]);
            ldsm4(bl, &Vql[brow * AST + bcol]);
#pragma unroll
            for (int nf = 0; nf < 2; nf++) {
                mma16816(cq[nf], ah, bh[nf * 2], bh[nf * 2 + 1]);
                mma16816(cq[nf], ah, bl[nf * 2], bl[nf * 2 + 1]);
                mma16816(cq[nf], al, bh[nf * 2], bh[nf * 2 + 1]);
            }
        }
        if (pf) {
#pragma unroll
            for (int j = 0; j < 4; j++) pvb[j] = src4[(j + 4) * 512 + tid];
        }
        if (kw > 0) {
#pragma unroll
            for (int nf = 0; nf < 2; nf++) {
                int col = nw * 16 + nf * 8 + 2 * t;
                float* s0 = &Sred[(kw - 1) * 1088 + (mw * 16 + g) * SRST + col];
                *reinterpret_cast<float2*>(s0) = make_float2(cq[nf][0], cq[nf][1]);
                *reinterpret_cast<float2*>(s0 + 8 * SRST) = make_float2(cq[nf][2], cq[nf][3]);
            }
        }
        __syncthreads();   // ---- sync A ----

        // V(ii+1) conversion into Vp buffer (freed by PV above)
        if (pf) {
#pragma unroll
            for (int j = 0; j < 4; j++) {
                int i1 = j * 512 + tid;
                int row = i1 >> 7, cc = (i1 & 127) * 4;
                split_store(pva[j], &Vph[row * AST + cc], &Vpl[row * AST + cc]);
            }
#pragma unroll
            for (int j = 0; j < 4; j++) {
                int i1 = (j + 4) * 512 + tid;
                int row = i1 >> 7, cc = (i1 & 127) * 4;
                split_store(pvb[j], &Vph[row * AST + cc], &Vpl[row * AST + cc]);
            }
        }
        // k-split reduce + row max (kw==0 warps)
        if (kw == 0) {
            float mA = -3e38f, mB = -3e38f;
#pragma unroll
            for (int nf = 0; nf < 2; nf++) {
                int col = nw * 16 + nf * 8 + 2 * t;
#pragma unroll
                for (int p = 0; p < 3; p++) {
                    float2 r0 = *reinterpret_cast<float2*>(&Sred[p * 1088 + (mw * 16 + g) * SRST + col]);
                    float2 r1 = *reinterpret_cast<float2*>(&Sred[p * 1088 + (mw * 16 + g + 8) * SRST + col]);
                    cq[nf][0] += r0.x; cq[nf][1] += r0.y;
                    cq[nf][2] += r1.x; cq[nf][3] += r1.y;
                }
                cq[nf][0] *= SCALE; cq[nf][1] *= SCALE;
                cq[nf][2] *= SCALE; cq[nf][3] *= SCALE;
                mA = fmaxf(mA, fmaxf(cq[nf][0], cq[nf][1]));
                mB = fmaxf(mB, fmaxf(cq[nf][2], cq[nf][3]));
            }
            mA = fmaxf(mA, __shfl_xor_sync(0xffffffffu, mA, 1));
            mA = fmaxf(mA, __shfl_xor_sync(0xffffffffu, mA, 2));
            mB = fmaxf(mB, __shfl_xor_sync(0xffffffffu, mB, 1));
            mB = fmaxf(mB, __shfl_xor_sync(0xffffffffu, mB, 2));
            if (t == 0) {
                wmax[nw * 32 + mw * 16 + g] = mA;
                wmax[nw * 32 + mw * 16 + g + 8] = mB;
            }
        }
        __syncthreads();   // ---- sync B ----

        // all warps: rescale cv by alpha(ii), computed locally
        {
            int rows[4] = {g, g + 8, 16 + g, 24 + g};
            float a_[4];
#pragma unroll
            for (int k = 0; k < 4; k++) {
                float mo = mrow[rows[k]];
                float cm = fmaxf(wmax[rows[k]], wmax[32 + rows[k]]);
                float mn = fmaxf(mo, cm);
                a_[k] = __expf(mo - mn);
            }
#pragma unroll
            for (int nj = 0; nj < 4; nj++) {
                cv[0][nj][0] *= a_[0]; cv[0][nj][1] *= a_[0];
                cv[0][nj][2] *= a_[1]; cv[0][nj][3] *= a_[1];
                cv[1][nj][0] *= a_[2]; cv[1][nj][1] *= a_[2];
                cv[1][nj][2] *= a_[3]; cv[1][nj][3] *= a_[3];
            }
        }
        // kw==0 warps: P = exp(s - m), write hi/lo + partial sums
        if (kw == 0) {
            int rA = mw * 16 + g;
            float moA = mrow[rA];
            float mA = fmaxf(moA, fmaxf(wmax[rA], wmax[32 + rA]));
            float moB = mrow[rA + 8];
            float mB = fmaxf(moB, fmaxf(wmax[rA + 8], wmax[32 + rA + 8]));
            float sA = 0.f, sB = 0.f;
#pragma unroll
            for (int nf = 0; nf < 2; nf++) {
                float p0 = __expf(cq[nf][0] - mA), p1 = __expf(cq[nf][1] - mA);
                float p2 = __expf(cq[nf][2] - mB), p3 = __expf(cq[nf][3] - mB);
                sA += p0 + p1; sB += p2 + p3;
                int col = nw * 16 + nf * 8 + 2 * t;
                __nv_bfloat16 h0 = __float2bfloat16(p0), h1 = __float2bfloat16(p1);
                __nv_bfloat16 h2 = __float2bfloat16(p2), h3 = __float2bfloat16(p3);
                *reinterpret_cast<uint32_t*>(&Ph[rA * PST + col]) = pack2(h0, h1);
                *reinterpret_cast<uint32_t*>(&Ph[(rA + 8) * PST + col]) = pack2(h2, h3);
                __nv_bfloat16 l0 = __float2bfloat16(p0 - __bfloat162float(h0));
                __nv_bfloat16 l1 = __float2bfloat16(p1 - __bfloat162float(h1));
                __nv_bfloat16 l2 = __float2bfloat16(p2 - __bfloat162float(h2));
                __nv_bfloat16 l3 = __float2bfloat16(p3 - __bfloat162float(h3));
                *reinterpret_cast<uint32_t*>(&Pl[rA * PST + col]) = pack2(l0, l1);
                *reinterpret_cast<uint32_t*>(&Pl[(rA + 8) * PST + col]) = pack2(l2, l3);
            }
            sA += __shfl_xor_sync(0xffffffffu, sA, 1);
            sA += __shfl_xor_sync(0xffffffffu, sA, 2);
            sB += __shfl_xor_sync(0xffffffffu, sB, 1);
            sB += __shfl_xor_sync(0xffffffffu, sB, 2);
            if (t == 0) { wsum[nw * 32 + rA] = sA; wsum[nw * 32 + rA + 8] = sB; }
        }
        __syncthreads();   // ---- sync C ----
    }

    // epilogue: final m/l update + PV for last chunk
    if (tid < 32) {
        float mo = mrow[tid];
        float cm = fmaxf(wmax[tid], wmax[32 + tid]);
        float mn = fmaxf(mo, cm);
        float a = __expf(mo - mn);
        lrow[tid] = lrow[tid] * a + wsum[tid] + wsum[32 + tid];
        mrow[tid] = mn;
    }
    {
        __nv_bfloat16* Vph = reinterpret_cast<__nv_bfloat16*>(smbuf + ((NCHUNK & 1) ? OFF_V0H : OFF_V1H));
        __nv_bfloat16* Vpl = reinterpret_cast<__nv_bfloat16*>(smbuf + ((NCHUNK & 1) ? OFF_V0L : OFF_V1L));
#pragma unroll
        for (int kk = 0; kk < 2; kk++) {
            int k0 = kk * 16;
            uint32_t ph[2][4], pl[2][4];
#pragma unroll
            for (int mi = 0; mi < 2; mi++) {
                ldsm4(ph[mi], &Ph[(mi * 16 + (lane & 15)) * PST + k0 + (lane >> 4) * 8]);
                ldsm4(pl[mi], &Pl[(mi * 16 + (lane & 15)) * PST + k0 + (lane >> 4) * 8]);
            }
#pragma unroll
            for (int j2 = 0; j2 < 2; j2++) {
                int vrow = k0 + (lane & 7) + (((lane >> 3) & 1) << 3);
                int vcol = warp * 32 + j2 * 16 + (lane >> 4) * 8;
                uint32_t vh[4], vl[4];
                ldsm4t(vh, &Vph[vrow * AST + vcol]);
                ldsm4t(vl, &Vpl[vrow * AST + vcol]);
#pragma unroll
                for (int half = 0; half < 2; half++)
#pragma unroll
                    for (int mi = 0; mi < 2; mi++) {
                        float* cc = cv[mi][j2 * 2 + half];
                        mma16816(cc, ph[mi], vh[half * 2], vh[half * 2 + 1]);
                        mma16816(cc, ph[mi], vl[half * 2], vl[half * 2 + 1]);
                        mma16816(cc, pl[mi], vh[half * 2], vh[half * 2 + 1]);
                    }
            }
        }
    }
    if (tid < 32) {
        g_m[(sp * B + b) * H + tid] = mrow[tid];
        g_l[(sp * B + b) * H + tid] = lrow[tid];
    }
#pragma unroll
    for (int mi = 0; mi < 2; mi++)
#pragma unroll
        for (int nj = 0; nj < 4; nj++) {
            int row = mi * 16 + g;
            int col = warp * 32 + nj * 8 + 2 * t;
            float* o = g_ctxp + ((size_t)(sp * B + b) * H + row) * R + col;
            *reinterpret_cast<float2*>(o) = make_float2(cv[mi][nj][0], cv[mi][nj][1]);
            *reinterpret_cast<float2*>(o + 8 * R) = make_float2(cv[mi][nj][2], cv[mi][nj][3]);
        }
}

// ---------------- combine ----------------
__global__ void combine_k() {
    int bh = blockIdx.x;
    __shared__ float w[NSPLIT];
    __shared__ float invL;
    if (threadIdx.x == 0) {
        float M = -3e38f;
#pragma unroll
        for (int sp = 0; sp < NSPLIT; sp++) M = fmaxf(M, g_m[sp * (B * H) + bh]);
        float L = 0.f;
#pragma unroll
        for (int sp = 0; sp < NSPLIT; sp++) {
            float ww = __expf(g_m[sp * (B * H) + bh] - M);
            w[sp] = ww;
            L += ww * g_l[sp * (B * H) + bh];
        }
        invL = 1.f / L;
    }
    __syncthreads();
    for (int r = threadIdx.x; r < R; r += blockDim.x) {
        float acc = 0.f;
#pragma unroll
        for (int sp = 0; sp < NSPLIT; sp++)
            acc += w[sp] * g_ctxp[((size_t)sp * (B * H) + bh) * R + r];
        g_ctx[(size_t)bh * R + r] = acc * invL;
    }
}

// ---------------- vabsorb ----------------
__global__ void vabsorb_k(const float* __restrict__ w_vc) {
    const int h = blockIdx.y;
    const int ks = blockIdx.x;
    __shared__ float As[32][33];
    __shared__ float Bs[32][132];
    const int tid = threadIdx.x;
    const int ty = tid / 32, tx = tid % 32;
    float acc[4][4] = {};
    for (int r0 = ks * 128; r0 < ks * 128 + 128; r0 += 32) {
        {
            int r = tid / 8, c = (tid % 8) * 4;
            float4 v = *reinterpret_cast<const float4*>(g_ctx + (size_t)(r * H + h) * R + r0 + c);
            As[r][c] = v.x; As[r][c + 1] = v.y; As[r][c + 2] = v.z; As[r][c + 3] = v.w;
        }
#pragma unroll
        for (int it = 0; it < 4; it++) {
            int i = tid + it * 256;
            int rr = i / 32, c = (i % 32) * 4;
            float4 v = *reinterpret_cast<const float4*>(w_vc + (size_t)(h * R + r0 + rr) * D + c);
            *reinterpret_cast<float4*>(&Bs[rr][c]) = v;
        }
        __syncthreads();
#pragma unroll
        for (int dd = 0; dd < 32; dd++) {
            float4 bv = *reinterpret_cast<float4*>(&Bs[dd][tx * 4]);
            float bb[4] = {bv.x, bv.y, bv.z, bv.w};
#pragma unroll
            for (int i = 0; i < 4; i++) {
                float a = As[ty * 4 + i][dd];
#pragma unroll
                for (int j = 0; j < 4; j++) acc[i][j] += a * bb[j];
            }
        }
        __syncthreads();
    }
#pragma unroll
    for (int i = 0; i < 4; i++)
#pragma unroll
        for (int j = 0; j < 4; j++)
            g_part[(ks * B + ty * 4 + i) * HID + h * D + tx * 4 + j] = acc[i][j];
}

// ---------------- launch ----------------
extern "C" void kernel_launch(void* const* d_in, const int* in_sizes, int n_in,
                              void* d_out, int out_size) {
    const float* hs   = (const float*)d_in[0];
    const float* ckv  = (const float*)d_in[1];
    const float* q_w  = (const float*)d_in[2];
    const float* q_b  = (const float*)d_in[3];
    const float* w_kc = (const float*)d_in[4];
    const float* w_vc = (const float*)d_in[5];
    const float* o_w  = (const float*)d_in[6];
    const float* o_b  = (const float*)d_in[7];
    float* out = (float*)d_out;

    float *pq, *pattn;
    cudaGetSymbolAddress((void**)&pq, g_q);
    cudaGetSymbolAddress((void**)&pattn, g_attn);
    cudaFuncSetAttribute(fmla_k, cudaFuncAttributeMaxDynamicSharedMemorySize, SMEM_FMLA);
    cudaFuncSetAttribute(gemm_bf_k, cudaFuncAttributeMaxDynamicSharedMemorySize, SMEM_GEMM);

    gemm_bf_k<<<dim3(32, 8), 256, SMEM_GEMM>>>(hs, q_w);
    reduce8_k<<<512, 256>>>(pq, q_b);
    qabsorb_k<<<dim3(4, 32), 256>>>(w_kc);
    fmla_k<<<dim3(NSPLIT, B), 512, SMEM_FMLA>>>(ckv);
    combine_k<<<B * H, 128>>>();
    vabsorb_k<<<dim3(4, 32), 256>>>(w_vc);
    reduce4_k<<<512, 256>>>(pattn, nullptr);
    gemm_bf_k<<<dim3(32, 8), 256, SMEM_GEMM>>>(pattn, o_w);
    reduce8_k<<<512, 256>>>(out, o_b);
}

// round 9
// speedup vs baseline: 1.0070x; 1.0070x over previous
#include <cuda_runtime.h>
#include <cuda_bf16.h>
#include <cstdint>

#define B 32
#define H 32
#define D 128
#define R 512
#define S 4096
#define HID 4096
#define SCALE 0.08838834764831845f
#define NSPLIT 4
#define SB (S / NSPLIT)
#define SC 32
#define NCHUNK (SB / SC)

// ---------------- scratch ----------------
__device__ float g_q[B * HID];
__device__ float g_part[8 * B * HID];
__device__ float g_qa[B * H * R];
__device__ float g_ctx[B * H * R];
__device__ float g_attn[B * HID];
__device__ float g_ctxp[8 * B * H * R];
__device__ float g_m[8 * B * H];
__device__ float g_l[8 * B * H];

// ---------------- helpers ----------------
__device__ __forceinline__ uint32_t pack2(__nv_bfloat16 a, __nv_bfloat16 b) {
    return (uint32_t)__bfloat16_as_ushort(a) | ((uint32_t)__bfloat16_as_ushort(b) << 16);
}
__device__ __forceinline__ void split_store(float4 v, __nv_bfloat16* hp, __nv_bfloat16* lp) {
    __nv_bfloat16 h0 = __float2bfloat16(v.x), h1 = __float2bfloat16(v.y),
                  h2 = __float2bfloat16(v.z), h3 = __float2bfloat16(v.w);
    __nv_bfloat16 l0 = __float2bfloat16(v.x - __bfloat162float(h0));
    __nv_bfloat16 l1 = __float2bfloat16(v.y - __bfloat162float(h1));
    __nv_bfloat16 l2 = __float2bfloat16(v.z - __bfloat162float(h2));
    __nv_bfloat16 l3 = __float2bfloat16(v.w - __bfloat162float(h3));
    *reinterpret_cast<uint2*>(hp) = make_uint2(pack2(h0, h1), pack2(h2, h3));
    *reinterpret_cast<uint2*>(lp) = make_uint2(pack2(l0, l1), pack2(l2, l3));
}
__device__ __forceinline__ uint32_t saddr(const void* p) {
    return (uint32_t)__cvta_generic_to_shared(p);
}
__device__ __forceinline__ void ldsm4(uint32_t* r, const void* p) {
    asm volatile("ldmatrix.sync.aligned.m8n8.x4.shared.b16 {%0,%1,%2,%3},[%4];\n"
                 : "=r"(r[0]), "=r"(r[1]), "=r"(r[2]), "=r"(r[3]) : "r"(saddr(p)));
}
__device__ __forceinline__ void ldsm4t(uint32_t* r, const void* p) {
    asm volatile("ldmatrix.sync.aligned.m8n8.x4.trans.shared.b16 {%0,%1,%2,%3},[%4];\n"
                 : "=r"(r[0]), "=r"(r[1]), "=r"(r[2]), "=r"(r[3]) : "r"(saddr(p)));
}
__device__ __forceinline__ void mma16816(float* c, const uint32_t* a, uint32_t b0, uint32_t b1) {
    asm volatile(
        "mma.sync.aligned.m16n8k16.row.col.f32.bf16.bf16.f32 "
        "{%0,%1,%2,%3},{%4,%5,%6,%7},{%8,%9},{%0,%1,%2,%3};\n"
        : "+f"(c[0]), "+f"(c[1]), "+f"(c[2]), "+f"(c[3])
        : "r"(a[0]), "r"(a[1]), "r"(a[2]), "r"(a[3]), "r"(b0), "r"(b1));
}

// ---------------- bf16 hi/lo GEMM-NT, split-K 8, double-buffered smem
#define GA 2560
#define GW 10240
#define G_A0H 0
#define G_A0L (GA)
#define G_A1H (2*GA)
#define G_A1L (3*GA)
#define G_W0H (4*GA)
#define G_W0L (4*GA + GW)
#define G_W1H (4*GA + 2*GW)
#define G_W1L (4*GA + 3*GW)
#define SMEM_GEMM (4*GA + 4*GW)

__global__ void __launch_bounds__(256) gemm_bf_k(const float* __restrict__ A,
                                                 const float* __restrict__ W) {
    extern __shared__ char gsm[];
    const int n0 = blockIdx.x * 128;
    const int ks = blockIdx.y;
    const int tid = threadIdx.x;
    const int warp = tid >> 5, lane = tid & 31;
    const int g = lane >> 2, t = lane & 3;
    float c[2][2][4] = {};

    const int ar = tid >> 3, ac = (tid & 7) * 4;
    {
        int k0 = ks * 512;
        float4 va = *reinterpret_cast<const float4*>(A + ar * HID + k0 + ac);
        split_store(va, (__nv_bfloat16*)(gsm + G_A0H) + ar * 40 + ac,
                        (__nv_bfloat16*)(gsm + G_A0L) + ar * 40 + ac);
#pragma unroll
        for (int it = 0; it < 4; it++) {
            int i = it * 256 + tid;
            int r = i >> 3, cc = (i & 7) * 4;
            float4 v = *reinterpret_cast<const float4*>(W + (size_t)(n0 + r) * HID + k0 + cc);
            split_store(v, (__nv_bfloat16*)(gsm + G_W0H) + r * 40 + cc,
                           (__nv_bfloat16*)(gsm + G_W0L) + r * 40 + cc);
        }
    }
    __syncthreads();

    for (int it16 = 0; it16 < 16; it16++) {
        const char* curA_h = gsm + ((it16 & 1) ? G_A1H : G_A0H);
        const char* curA_l = gsm + ((it16 & 1) ? G_A1L : G_A0L);
        const char* curW_h = gsm + ((it16 & 1) ? G_W1H : G_W0H);
        const char* curW_l = gsm + ((it16 & 1) ? G_W1L : G_W0L);
        char* nxtA_h = gsm + ((it16 & 1) ? G_A0H : G_A1H);
        char* nxtA_l = gsm + ((it16 & 1) ? G_A0L : G_A1L);
        char* nxtW_h = gsm + ((it16 & 1) ? G_W0H : G_W1H);
        char* nxtW_l = gsm + ((it16 & 1) ? G_W0L : G_W1L);
        bool pf = (it16 + 1) < 16;
        float4 va, vw[4];
        if (pf) {
            int k0 = ks * 512 + (it16 + 1) * 32;
            va = *reinterpret_cast<const float4*>(A + ar * HID + k0 + ac);
#pragma unroll
            for (int itw = 0; itw < 4; itw++) {
                int i = itw * 256 + tid;
                vw[itw] = *reinterpret_cast<const float4*>(
                    W + (size_t)(n0 + (i >> 3)) * HID + k0 + ((i & 7) * 4));
            }
        }
#pragma unroll
        for (int kk = 0; kk < 2; kk++) {
            uint32_t ah[2][4], al[2][4];
#pragma unroll
            for (int mi = 0; mi < 2; mi++) {
                ldsm4(ah[mi], (const __nv_bfloat16*)curA_h + (mi * 16 + (lane & 15)) * 40 + kk * 16 + (lane >> 4) * 8);
                ldsm4(al[mi], (const __nv_bfloat16*)curA_l + (mi * 16 + (lane & 15)) * 40 + kk * 16 + (lane >> 4) * 8);
            }
            int brow = warp * 16 + ((lane >> 4) << 3) + (lane & 7);
            int bcol = kk * 16 + (((lane >> 3) & 1) << 3);
            uint32_t bh[4], bl[4];
            ldsm4(bh, (const __nv_bfloat16*)curW_h + brow * 40 + bcol);
            ldsm4(bl, (const __nv_bfloat16*)curW_l + brow * 40 + bcol);
#pragma unroll
            for (int nf = 0; nf < 2; nf++)
#pragma unroll
                for (int mi = 0; mi < 2; mi++)
                    mma16816(c[mi][nf], ah[mi], bh[nf * 2], bh[nf * 2 + 1]);
#pragma unroll
            for (int nf = 0; nf < 2; nf++)
#pragma unroll
                for (int mi = 0; mi < 2; mi++)
                    mma16816(c[mi][nf], ah[mi], bl[nf * 2], bl[nf * 2 + 1]);
#pragma unroll
            for (int nf = 0; nf < 2; nf++)
#pragma unroll
                for (int mi = 0; mi < 2; mi++)
                    mma16816(c[mi][nf], al[mi], bh[nf * 2], bh[nf * 2 + 1]);
        }
        if (pf) {
            split_store(va, (__nv_bfloat16*)nxtA_h + ar * 40 + ac,
                            (__nv_bfloat16*)nxtA_l + ar * 40 + ac);
#pragma unroll
            for (int itw = 0; itw < 4; itw++) {
                int i = itw * 256 + tid;
                int r = i >> 3, cc = (i & 7) * 4;
                split_store(vw[itw], (__nv_bfloat16*)nxtW_h + r * 40 + cc,
                                     (__nv_bfloat16*)nxtW_l + r * 40 + cc);
            }
        }
        __syncthreads();
    }
#pragma unroll
    for (int mi = 0; mi < 2; mi++)
#pragma unroll
        for (int nf = 0; nf < 2; nf++) {
            int row = mi * 16 + g;
            int col = n0 + warp * 16 + nf * 8 + 2 * t;
            float* o = g_part + ks * (B * HID) + (size_t)row * HID + col;
            *reinterpret_cast<float2*>(o) = make_float2(c[mi][nf][0], c[mi][nf][1]);
            *reinterpret_cast<float2*>(o + 8 * HID) = make_float2(c[mi][nf][2], c[mi][nf][3]);
        }
}

// ---------------- reduces
__global__ void reduce8_k(float* __restrict__ dst, const float* __restrict__ bias) {
    int i = blockIdx.x * 256 + threadIdx.x;
    float v = 0.f;
#pragma unroll
    for (int s = 0; s < 8; s++) v += g_part[s * 131072 + i];
    if (bias) v += bias[i & (HID - 1)];
    dst[i] = v;
}
__global__ void reduce4_k(float* __restrict__ dst, const float* __restrict__ bias) {
    int i = blockIdx.x * 256 + threadIdx.x;
    float v = g_part[i] + g_part[131072 + i] + g_part[2 * 131072 + i] + g_part[3 * 131072 + i];
    if (bias) v += bias[i & (HID - 1)];
    dst[i] = v;
}

// ---------------- q_absorbed
__global__ void qabsorb_k(const float* __restrict__ w_kc) {
    const int h = blockIdx.y;
    const int r0 = blockIdx.x * 128;
    __shared__ float As[32][33];
    __shared__ float Bs[32][132];
    const int tid = threadIdx.x;
    const int ty = tid / 32, tx = tid % 32;
    float acc[4][4] = {};
    for (int d0 = 0; d0 < 128; d0 += 32) {
        {
            int r = tid / 8, c = (tid % 8) * 4;
            float4 v = *reinterpret_cast<const float4*>(g_q + r * HID + h * D + d0 + c);
            As[r][c] = v.x; As[r][c + 1] = v.y; As[r][c + 2] = v.z; As[r][c + 3] = v.w;
        }
#pragma unroll
        for (int it = 0; it < 4; it++) {
            int i = tid + it * 256;
            int rr = i / 32, c = (i % 32) * 4;
            float4 v = *reinterpret_cast<const float4*>(w_kc + (size_t)(h * D + d0 + rr) * R + r0 + c);
            *reinterpret_cast<float4*>(&Bs[rr][c]) = v;
        }
        __syncthreads();
#pragma unroll
        for (int dd = 0; dd < 32; dd++) {
            float4 bv = *reinterpret_cast<float4*>(&Bs[dd][tx * 4]);
            float bb[4] = {bv.x, bv.y, bv.z, bv.w};
#pragma unroll
            for (int i = 0; i < 4; i++) {
                float a = As[ty * 4 + i][dd];
#pragma unroll
                for (int j = 0; j < 4; j++) acc[i][j] += a * bb[j];
            }
        }
        __syncthreads();
    }
#pragma unroll
    for (int i = 0; i < 4; i++)
#pragma unroll
        for (int j = 0; j < 4; j++)
            g_qa[((ty * 4 + i) * H + h) * R + r0 + tx * 4 + j] = acc[i][j];
}

// ---------------- fused flash MLA: 512 threads, split accumulators, low reg pressure ----------------
#define AST 520
#define PST 40
#define SRST 34
#define OFF_AH 0
#define OFF_AL 33280
#define OFF_V0H 66560
#define OFF_V0L 99840
#define OFF_V1H 133120
#define OFF_V1L 166400
#define OFF_PH 199680
#define OFF_PL 202240
#define OFF_SRED 204800
#define OFF_WMAX 217856
#define OFF_WSUM 218112
#define OFF_MROW 218368
#define OFF_LROW 218496
#define SMEM_FMLA 218624

__global__ void __launch_bounds__(512, 1) fmla_k(const float* __restrict__ ckv) {
    extern __shared__ char smbuf[];
    __nv_bfloat16* Ah = reinterpret_cast<__nv_bfloat16*>(smbuf + OFF_AH);
    __nv_bfloat16* Al = reinterpret_cast<__nv_bfloat16*>(smbuf + OFF_AL);
    __nv_bfloat16* Ph = reinterpret_cast<__nv_bfloat16*>(smbuf + OFF_PH);
    __nv_bfloat16* Pl = reinterpret_cast<__nv_bfloat16*>(smbuf + OFF_PL);
    float* Sred = reinterpret_cast<float*>(smbuf + OFF_SRED);
    float* wmax = reinterpret_cast<float*>(smbuf + OFF_WMAX);
    float* wsum = reinterpret_cast<float*>(smbuf + OFF_WSUM);
    float* mrow = reinterpret_cast<float*>(smbuf + OFF_MROW);
    float* lrow = reinterpret_cast<float*>(smbuf + OFF_LROW);

    const int sp = blockIdx.x, b = blockIdx.y;
    const int tid = threadIdx.x;
    const int warp = tid >> 5, lane = tid & 31;
    const int g = lane >> 2, t = lane & 3;
    const int kw = warp >> 2;
    const int mw = (warp >> 1) & 1;
    const int nw = warp & 1;

    // prologue: A and V(0)
#pragma unroll
    for (int it = 0; it < 8; it++) {
        int i = it * 512 + tid;
        int row = i >> 7, cc = (i & 127) * 4;
        float4 v = *reinterpret_cast<const float4*>(g_qa + (size_t)(b * H + row) * R + cc);
        split_store(v, &Ah[row * AST + cc], &Al[row * AST + cc]);
    }
    {
        const float4* src4 = reinterpret_cast<const float4*>(ckv + ((size_t)b * S + sp * SB) * R);
        __nv_bfloat16* Vh = reinterpret_cast<__nv_bfloat16*>(smbuf + OFF_V0H);
        __nv_bfloat16* Vl = reinterpret_cast<__nv_bfloat16*>(smbuf + OFF_V0L);
#pragma unroll
        for (int it = 0; it < 8; it++) {
            int i = it * 512 + tid;
            int row = i >> 7, cc = (i & 127) * 4;
            split_store(src4[i], &Vh[row * AST + cc], &Vl[row * AST + cc]);
        }
    }
    if (tid < 32) { mrow[tid] = -3e38f; lrow[tid] = 0.f; }
    __syncthreads();

    float cv[2][4][4] = {};

    for (int ii = 0; ii < NCHUNK; ii++) {
        __nv_bfloat16* Vqh = reinterpret_cast<__nv_bfloat16*>(smbuf + ((ii & 1) ? OFF_V1H : OFF_V0H));
        __nv_bfloat16* Vql = reinterpret_cast<__nv_bfloat16*>(smbuf + ((ii & 1) ? OFF_V1L : OFF_V0L));
        __nv_bfloat16* Vph = reinterpret_cast<__nv_bfloat16*>(smbuf + ((ii & 1) ? OFF_V0H : OFF_V1H));
        __nv_bfloat16* Vpl = reinterpret_cast<__nv_bfloat16*>(smbuf + ((ii & 1) ? OFF_V0L : OFF_V1L));
        const bool pf = (ii + 1) < NCHUNK;

        // running m/l update for chunk ii-1 (off critical path)
        if (tid < 32 && ii > 0) {
            float mo = mrow[tid];
            float cm = fmaxf(wmax[tid], wmax[32 + tid]);
            float mn = fmaxf(mo, cm);
            float a = __expf(mo - mn);
            lrow[tid] = lrow[tid] * a + wsum[tid] + wsum[32 + tid];
            mrow[tid] = mn;
        }

        const float4* src4 = reinterpret_cast<const float4*>(
            ckv + ((size_t)b * S + sp * SB + (ii + 1) * SC) * R);
        float4 pv[4];
        if (pf) {
#pragma unroll
            for (int j = 0; j < 4; j++) pv[j] = src4[j * 512 + tid];
        }

        // ---- PV for chunk ii-1 (term-outer order: acc reuse distance 4) ----
        if (ii > 0) {
#pragma unroll
            for (int kk = 0; kk < 2; kk++) {
                int k0 = kk * 16;
                uint32_t ph[2][4], pl[2][4];
#pragma unroll
                for (int mi = 0; mi < 2; mi++) {
                    ldsm4(ph[mi], &Ph[(mi * 16 + (lane & 15)) * PST + k0 + (lane >> 4) * 8]);
                    ldsm4(pl[mi], &Pl[(mi * 16 + (lane & 15)) * PST + k0 + (lane >> 4) * 8]);
                }
#pragma unroll
                for (int j2 = 0; j2 < 2; j2++) {
                    int vrow = k0 + (lane & 7) + (((lane >> 3) & 1) << 3);
                    int vcol = warp * 32 + j2 * 16 + (lane >> 4) * 8;
                    uint32_t vh[4], vl[4];
                    ldsm4t(vh, &Vph[vrow * AST + vcol]);
                    ldsm4t(vl, &Vpl[vrow * AST + vcol]);
#pragma unroll
                    for (int half = 0; half < 2; half++)
#pragma unroll
                        for (int mi = 0; mi < 2; mi++)
                            mma16816(cv[mi][j2 * 2 + half], ph[mi], vh[half * 2], vh[half * 2 + 1]);
#pragma unroll
                    for (int half = 0; half < 2; half++)
#pragma unroll
                        for (int mi = 0; mi < 2; mi++)
                            mma16816(cv[mi][j2 * 2 + half], ph[mi], vl[half * 2], vl[half * 2 + 1]);
#pragma unroll
                    for (int half = 0; half < 2; half++)
#pragma unroll
                        for (int mi = 0; mi < 2; mi++)
                            mma16816(cv[mi][j2 * 2 + half], pl[mi], vh[half * 2], vh[half * 2 + 1]);
                }
            }
        }
        __syncthreads();   // ---- sync D : Vp free ----

        // convert V(ii+1) first half; frees pv regs before QK
        if (pf) {
#pragma unroll
            for (int j = 0; j < 4; j++) {
                int i1 = j * 512 + tid;
                int row = i1 >> 7, cc = (i1 & 127) * 4;
                split_store(pv[j], &Vph[row * AST + cc], &Vpl[row * AST + cc]);
            }
#pragma unroll
            for (int j = 0; j < 4; j++) pv[j] = src4[(j + 4) * 512 + tid];
        }

        // ---- QK for chunk ii : 3 split accumulator sets ----
        float cqA[2][4] = {}, cqB[2][4] = {}, cqC[2][4] = {};
#pragma unroll
        for (int kk = 0; kk < 8; kk++) {
            int k0 = kw * 128 + kk * 16;
            uint32_t ah[4], al[4];
            ldsm4(ah, &Ah[(mw * 16 + (lane & 15)) * AST + k0 + (lane >> 4) * 8]);
            ldsm4(al, &Al[(mw * 16 + (lane & 15)) * AST + k0 + (lane >> 4) * 8]);
            int brow = nw * 16 + ((lane >> 4) << 3) + (lane & 7);
            int bcol = k0 + (((lane >> 3) & 1) << 3);
            uint32_t bh[4], bl[4];
            ldsm4(bh, &Vqh[brow * AST + bcol]);
            ldsm4(bl, &Vql[brow * AST + bcol]);
#pragma unroll
            for (int nf = 0; nf < 2; nf++) mma16816(cqA[nf], ah, bh[nf * 2], bh[nf * 2 + 1]);
#pragma unroll
            for (int nf = 0; nf < 2; nf++) mma16816(cqB[nf], ah, bl[nf * 2], bl[nf * 2 + 1]);
#pragma unroll
            for (int nf = 0; nf < 2; nf++) mma16816(cqC[nf], al, bh[nf * 2], bh[nf * 2 + 1]);
        }
        float cq[2][4];
#pragma unroll
        for (int nf = 0; nf < 2; nf++)
#pragma unroll
            for (int i2 = 0; i2 < 4; i2++)
                cq[nf][i2] = cqA[nf][i2] + cqB[nf][i2] + cqC[nf][i2];
        if (kw > 0) {
#pragma unroll
            for (int nf = 0; nf < 2; nf++) {
                int col = nw * 16 + nf * 8 + 2 * t;
                float* s0 = &Sred[(kw - 1) * 1088 + (mw * 16 + g) * SRST + col];
                *reinterpret_cast<float2*>(s0) = make_float2(cq[nf][0], cq[nf][1]);
                *reinterpret_cast<float2*>(s0 + 8 * SRST) = make_float2(cq[nf][2], cq[nf][3]);
            }
        }
        __syncthreads();   // ---- sync A ----

        // convert V(ii+1) second half (overlaps kw0 reduce)
        if (pf) {
#pragma unroll
            for (int j = 0; j < 4; j++) {
                int i1 = (j + 4) * 512 + tid;
                int row = i1 >> 7, cc = (i1 & 127) * 4;
                split_store(pv[j], &Vph[row * AST + cc], &Vpl[row * AST + cc]);
            }
        }
        // k-split reduce + row max (kw==0 warps)
        if (kw == 0) {
            float mA = -3e38f, mB = -3e38f;
#pragma unroll
            for (int nf = 0; nf < 2; nf++) {
                int col = nw * 16 + nf * 8 + 2 * t;
#pragma unroll
                for (int p = 0; p < 3; p++) {
                    float2 r0 = *reinterpret_cast<float2*>(&Sred[p * 1088 + (mw * 16 + g) * SRST + col]);
                    float2 r1 = *reinterpret_cast<float2*>(&Sred[p * 1088 + (mw * 16 + g + 8) * SRST + col]);
                    cq[nf][0] += r0.x; cq[nf][1] += r0.y;
                    cq[nf][2] += r1.x; cq[nf][3] += r1.y;
                }
                cq[nf][0] *= SCALE; cq[nf][1] *= SCALE;
                cq[nf][2] *= SCALE; cq[nf][3] *= SCALE;
                mA = fmaxf(mA, fmaxf(cq[nf][0], cq[nf][1]));
                mB = fmaxf(mB, fmaxf(cq[nf][2], cq[nf][3]));
            }
            mA = fmaxf(mA, __shfl_xor_sync(0xffffffffu, mA, 1));
            mA = fmaxf(mA, __shfl_xor_sync(0xffffffffu, mA, 2));
            mB = fmaxf(mB, __shfl_xor_sync(0xffffffffu, mB, 1));
            mB = fmaxf(mB, __shfl_xor_sync(0xffffffffu, mB, 2));
            if (t == 0) {
                wmax[nw * 32 + mw * 16 + g] = mA;
                wmax[nw * 32 + mw * 16 + g + 8] = mB;
            }
        }
        __syncthreads();   // ---- sync B ----

        // all warps: rescale cv by alpha(ii), computed locally
        {
            int rows[4] = {g, g + 8, 16 + g, 24 + g};
            float a_[4];
#pragma unroll
            for (int k = 0; k < 4; k++) {
                float mo = mrow[rows[k]];
                float cm = fmaxf(wmax[rows[k]], wmax[32 + rows[k]]);
                float mn = fmaxf(mo, cm);
                a_[k] = __expf(mo - mn);
            }
#pragma unroll
            for (int nj = 0; nj < 4; nj++) {
                cv[0][nj][0] *= a_[0]; cv[0][nj][1] *= a_[0];
                cv[0][nj][2] *= a_[1]; cv[0][nj][3] *= a_[1];
                cv[1][nj][0] *= a_[2]; cv[1][nj][1] *= a_[2];
                cv[1][nj][2] *= a_[3]; cv[1][nj][3] *= a_[3];
            }
        }
        // kw==0 warps: P = exp(s - m), write hi/lo + partial sums
        if (kw == 0) {
            int rA = mw * 16 + g;
            float mA = fmaxf(mrow[rA], fmaxf(wmax[rA], wmax[32 + rA]));
            float mB = fmaxf(mrow[rA + 8], fmaxf(wmax[rA + 8], wmax[32 + rA + 8]));
            float sA = 0.f, sB = 0.f;
#pragma unroll
            for (int nf = 0; nf < 2; nf++) {
                float p0 = __expf(cq[nf][0] - mA), p1 = __expf(cq[nf][1] - mA);
                float p2 = __expf(cq[nf][2] - mB), p3 = __expf(cq[nf][3] - mB);
                sA += p0 + p1; sB += p2 + p3;
                int col = nw * 16 + nf * 8 + 2 * t;
                __nv_bfloat16 h0 = __float2bfloat16(p0), h1 = __float2bfloat16(p1);
                __nv_bfloat16 h2 = __float2bfloat16(p2), h3 = __float2bfloat16(p3);
                *reinterpret_cast<uint32_t*>(&Ph[rA * PST + col]) = pack2(h0, h1);
                *reinterpret_cast<uint32_t*>(&Ph[(rA + 8) * PST + col]) = pack2(h2, h3);
                __nv_bfloat16 l0 = __float2bfloat16(p0 - __bfloat162float(h0));
                __nv_bfloat16 l1 = __float2bfloat16(p1 - __bfloat162float(h1));
                __nv_bfloat16 l2 = __float2bfloat16(p2 - __bfloat162float(h2));
                __nv_bfloat16 l3 = __float2bfloat16(p3 - __bfloat162float(h3));
                *reinterpret_cast<uint32_t*>(&Pl[rA * PST + col]) = pack2(l0, l1);
                *reinterpret_cast<uint32_t*>(&Pl[(rA + 8) * PST + col]) = pack2(l2, l3);
            }
            sA += __shfl_xor_sync(0xffffffffu, sA, 1);
            sA += __shfl_xor_sync(0xffffffffu, sA, 2);
            sB += __shfl_xor_sync(0xffffffffu, sB, 1);
            sB += __shfl_xor_sync(0xffffffffu, sB, 2);
            if (t == 0) { wsum[nw * 32 + rA] = sA; wsum[nw * 32 + rA + 8] = sB; }
        }
        __syncthreads();   // ---- sync C ----
    }

    // epilogue: final m/l update + PV for last chunk
    if (tid < 32) {
        float mo = mrow[tid];
        float cm = fmaxf(wmax[tid], wmax[32 + tid]);
        float mn = fmaxf(mo, cm);
        float a = __expf(mo - mn);
        lrow[tid] = lrow[tid] * a + wsum[tid] + wsum[32 + tid];
        mrow[tid] = mn;
    }
    {
        __nv_bfloat16* Vph = reinterpret_cast<__nv_bfloat16*>(smbuf + ((NCHUNK & 1) ? OFF_V0H : OFF_V1H));
        __nv_bfloat16* Vpl = reinterpret_cast<__nv_bfloat16*>(smbuf + ((NCHUNK & 1) ? OFF_V0L : OFF_V1L));
#pragma unroll
        for (int kk = 0; kk < 2; kk++) {
            int k0 = kk * 16;
            uint32_t ph[2][4], pl[2][4];
#pragma unroll
            for (int mi = 0; mi < 2; mi++) {
                ldsm4(ph[mi], &Ph[(mi * 16 + (lane & 15)) * PST + k0 + (lane >> 4) * 8]);
                ldsm4(pl[mi], &Pl[(mi * 16 + (lane & 15)) * PST + k0 + (lane >> 4) * 8]);
            }
#pragma unroll
            for (int j2 = 0; j2 < 2; j2++) {
                int vrow = k0 + (lane & 7) + (((lane >> 3) & 1) << 3);
                int vcol = warp * 32 + j2 * 16 + (lane >> 4) * 8;
                uint32_t vh[4], vl[4];
                ldsm4t(vh, &Vph[vrow * AST + vcol]);
                ldsm4t(vl, &Vpl[vrow * AST + vcol]);
#pragma unroll
                for (int half = 0; half < 2; half++)
#pragma unroll
                    for (int mi = 0; mi < 2; mi++)
                        mma16816(cv[mi][j2 * 2 + half], ph[mi], vh[half * 2], vh[half * 2 + 1]);
#pragma unroll
                for (int half = 0; half < 2; half++)
#pragma unroll
                    for (int mi = 0; mi < 2; mi++)
                        mma16816(cv[mi][j2 * 2 + half], ph[mi], vl[half * 2], vl[half * 2 + 1]);
#pragma unroll
                for (int half = 0; half < 2; half++)
#pragma unroll
                    for (int mi = 0; mi < 2; mi++)
                        mma16816(cv[mi][j2 * 2 + half], pl[mi], vh[half * 2], vh[half * 2 + 1]);
            }
        }
    }
    if (tid < 32) {
        g_m[(sp * B + b) * H + tid] = mrow[tid];
        g_l[(sp * B + b) * H + tid] = lrow[tid];
    }
#pragma unroll
    for (int mi = 0; mi < 2; mi++)
#pragma unroll
        for (int nj = 0; nj < 4; nj++) {
            int row = mi * 16 + g;
            int col = warp * 32 + nj * 8 + 2 * t;
            float* o = g_ctxp + ((size_t)(sp * B + b) * H + row) * R + col;
            *reinterpret_cast<float2*>(o) = make_float2(cv[mi][nj][0], cv[mi][nj][1]);
            *reinterpret_cast<float2*>(o + 8 * R) = make_float2(cv[mi][nj][2], cv[mi][nj][3]);
        }
}

// ---------------- combine ----------------
__global__ void combine_k() {
    int bh = blockIdx.x;
    __shared__ float w[NSPLIT];
    __shared__ float invL;
    if (threadIdx.x == 0) {
        float M = -3e38f;
#pragma unroll
        for (int sp = 0; sp < NSPLIT; sp++) M = fmaxf(M, g_m[sp * (B * H) + bh]);
        float L = 0.f;
#pragma unroll
        for (int sp = 0; sp < NSPLIT; sp++) {
            float ww = __expf(g_m[sp * (B * H) + bh] - M);
            w[sp] = ww;
            L += ww * g_l[sp * (B * H) + bh];
        }
        invL = 1.f / L;
    }
    __syncthreads();
    for (int r = threadIdx.x; r < R; r += blockDim.x) {
        float acc = 0.f;
#pragma unroll
        for (int sp = 0; sp < NSPLIT; sp++)
            acc += w[sp] * g_ctxp[((size_t)sp * (B * H) + bh) * R + r];
        g_ctx[(size_t)bh * R + r] = acc * invL;
    }
}

// ---------------- vabsorb ----------------
__global__ void vabsorb_k(const float* __restrict__ w_vc) {
    const int h = blockIdx.y;
    const int ks = blockIdx.x;
    __shared__ float As[32][33];
    __shared__ float Bs[32][132];
    const int tid = threadIdx.x;
    const int ty = tid / 32, tx = tid % 32;
    float acc[4][4] = {};
    for (int r0 = ks * 128; r0 < ks * 128 + 128; r0 += 32) {
        {
            int r = tid / 8, c = (tid % 8) * 4;
            float4 v = *reinterpret_cast<const float4*>(g_ctx + (size_t)(r * H + h) * R + r0 + c);
            As[r][c] = v.x; As[r][c + 1] = v.y; As[r][c + 2] = v.z; As[r][c + 3] = v.w;
        }
#pragma unroll
        for (int it = 0; it < 4; it++) {
            int i = tid + it * 256;
            int rr = i / 32, c = (i % 32) * 4;
            float4 v = *reinterpret_cast<const float4*>(w_vc + (size_t)(h * R + r0 + rr) * D + c);
            *reinterpret_cast<float4*>(&Bs[rr][c]) = v;
        }
        __syncthreads();
#pragma unroll
        for (int dd = 0; dd < 32; dd++) {
            float4 bv = *reinterpret_cast<float4*>(&Bs[dd][tx * 4]);
            float bb[4] = {bv.x, bv.y, bv.z, bv.w};
#pragma unroll
            for (int i = 0; i < 4; i++) {
                float a = As[ty * 4 + i][dd];
#pragma unroll
                for (int j = 0; j < 4; j++) acc[i][j] += a * bb[j];
            }
        }
        __syncthreads();
    }
#pragma unroll
    for (int i = 0; i < 4; i++)
#pragma unroll
        for (int j = 0; j < 4; j++)
            g_part[(ks * B + ty * 4 + i) * HID + h * D + tx * 4 + j] = acc[i][j];
}

// ---------------- launch ----------------
extern "C" void kernel_launch(void* const* d_in, const int* in_sizes, int n_in,
                              void* d_out, int out_size) {
    const float* hs   = (const float*)d_in[0];
    const float* ckv  = (const float*)d_in[1];
    const float* q_w  = (const float*)d_in[2];
    const float* q_b  = (const float*)d_in[3];
    const float* w_kc = (const float*)d_in[4];
    const float* w_vc = (const float*)d_in[5];
    const float* o_w  = (const float*)d_in[6];
    const float* o_b  = (const float*)d_in[7];
    float* out = (float*)d_out;

    float *pq, *pattn;
    cudaGetSymbolAddress((void**)&pq, g_q);
    cudaGetSymbolAddress((void**)&pattn, g_attn);
    cudaFuncSetAttribute(fmla_k, cudaFuncAttributeMaxDynamicSharedMemorySize, SMEM_FMLA);
    cudaFuncSetAttribute(gemm_bf_k, cudaFuncAttributeMaxDynamicSharedMemorySize, SMEM_GEMM);

    gemm_bf_k<<<dim3(32, 8), 256, SMEM_GEMM>>>(hs, q_w);
    reduce8_k<<<512, 256>>>(pq, q_b);
    qabsorb_k<<<dim3(4, 32), 256>>>(w_kc);
    fmla_k<<<dim3(NSPLIT, B), 512, SMEM_FMLA>>>(ckv);
    combine_k<<<B * H, 128>>>();
    vabsorb_k<<<dim3(4, 32), 256>>>(w_vc);
    reduce4_k<<<512, 256>>>(pattn, nullptr);
    gemm_bf_k<<<dim3(32, 8), 256, SMEM_GEMM>>>(pattn, o_w);
    reduce8_k<<<512, 256>>>(out, o_b);
}

// round 10
// speedup vs baseline: 1.0081x; 1.0011x over previous
#include <cuda_runtime.h>
#include <cuda_bf16.h>
#include <cstdint>

#define B 32
#define H 32
#define D 128
#define R 512
#define S 4096
#define HID 4096
#define SCALE 0.08838834764831845f
#define NSPLIT 4
#define SB (S / NSPLIT)
#define SC 32
#define NCHUNK (SB / SC)

// ---------------- scratch ----------------
__device__ float g_q[B * HID];
__device__ float g_part[8 * B * HID];
__device__ float g_qa[B * H * R];
__device__ float g_ctx[B * H * R];
__device__ float g_attn[B * HID];
__device__ float g_ctxp[8 * B * H * R];
__device__ float g_m[8 * B * H];
__device__ float g_l[8 * B * H];

// ---------------- helpers ----------------
__device__ __forceinline__ uint32_t pack2(__nv_bfloat16 a, __nv_bfloat16 b) {
    return (uint32_t)__bfloat16_as_ushort(a) | ((uint32_t)__bfloat16_as_ushort(b) << 16);
}
__device__ __forceinline__ void split_store(float4 v, __nv_bfloat16* hp, __nv_bfloat16* lp) {
    __nv_bfloat16 h0 = __float2bfloat16(v.x), h1 = __float2bfloat16(v.y),
                  h2 = __float2bfloat16(v.z), h3 = __float2bfloat16(v.w);
    __nv_bfloat16 l0 = __float2bfloat16(v.x - __bfloat162float(h0));
    __nv_bfloat16 l1 = __float2bfloat16(v.y - __bfloat162float(h1));
    __nv_bfloat16 l2 = __float2bfloat16(v.z - __bfloat162float(h2));
    __nv_bfloat16 l3 = __float2bfloat16(v.w - __bfloat162float(h3));
    *reinterpret_cast<uint2*>(hp) = make_uint2(pack2(h0, h1), pack2(h2, h3));
    *reinterpret_cast<uint2*>(lp) = make_uint2(pack2(l0, l1), pack2(l2, l3));
}
__device__ __forceinline__ uint32_t saddr(const void* p) {
    return (uint32_t)__cvta_generic_to_shared(p);
}
__device__ __forceinline__ void ldsm4(uint32_t* r, const void* p) {
    asm volatile("ldmatrix.sync.aligned.m8n8.x4.shared.b16 {%0,%1,%2,%3},[%4];\n"
                 : "=r"(r[0]), "=r"(r[1]), "=r"(r[2]), "=r"(r[3]) : "r"(saddr(p)));
}
__device__ __forceinline__ void ldsm4t(uint32_t* r, const void* p) {
    asm volatile("ldmatrix.sync.aligned.m8n8.x4.trans.shared.b16 {%0,%1,%2,%3},[%4];\n"
                 : "=r"(r[0]), "=r"(r[1]), "=r"(r[2]), "=r"(r[3]) : "r"(saddr(p)));
}
__device__ __forceinline__ void mma16816(float* c, const uint32_t* a, uint32_t b0, uint32_t b1) {
    asm volatile(
        "mma.sync.aligned.m16n8k16.row.col.f32.bf16.bf16.f32 "
        "{%0,%1,%2,%3},{%4,%5,%6,%7},{%8,%9},{%0,%1,%2,%3};\n"
        : "+f"(c[0]), "+f"(c[1]), "+f"(c[2]), "+f"(c[3])
        : "r"(a[0]), "r"(a[1]), "r"(a[2]), "r"(a[3]), "r"(b0), "r"(b1));
}

// ---------------- bf16 hi/lo GEMM-NT, split-K 8, double-buffered smem
#define GA 2560
#define GW 10240
#define G_A0H 0
#define G_A0L (GA)
#define G_A1H (2*GA)
#define G_A1L (3*GA)
#define G_W0H (4*GA)
#define G_W0L (4*GA + GW)
#define G_W1H (4*GA + 2*GW)
#define G_W1L (4*GA + 3*GW)
#define SMEM_GEMM (4*GA + 4*GW)

__global__ void __launch_bounds__(256) gemm_bf_k(const float* __restrict__ A,
                                                 const float* __restrict__ W) {
    extern __shared__ char gsm[];
    const int n0 = blockIdx.x * 128;
    const int ks = blockIdx.y;
    const int tid = threadIdx.x;
    const int warp = tid >> 5, lane = tid & 31;
    const int g = lane >> 2, t = lane & 3;
    float c[2][2][4] = {};

    const int ar = tid >> 3, ac = (tid & 7) * 4;
    {
        int k0 = ks * 512;
        float4 va = *reinterpret_cast<const float4*>(A + ar * HID + k0 + ac);
        split_store(va, (__nv_bfloat16*)(gsm + G_A0H) + ar * 40 + ac,
                        (__nv_bfloat16*)(gsm + G_A0L) + ar * 40 + ac);
#pragma unroll
        for (int it = 0; it < 4; it++) {
            int i = it * 256 + tid;
            int r = i >> 3, cc = (i & 7) * 4;
            float4 v = *reinterpret_cast<const float4*>(W + (size_t)(n0 + r) * HID + k0 + cc);
            split_store(v, (__nv_bfloat16*)(gsm + G_W0H) + r * 40 + cc,
                           (__nv_bfloat16*)(gsm + G_W0L) + r * 40 + cc);
        }
    }
    __syncthreads();

    for (int it16 = 0; it16 < 16; it16++) {
        const char* curA_h = gsm + ((it16 & 1) ? G_A1H : G_A0H);
        const char* curA_l = gsm + ((it16 & 1) ? G_A1L : G_A0L);
        const char* curW_h = gsm + ((it16 & 1) ? G_W1H : G_W0H);
        const char* curW_l = gsm + ((it16 & 1) ? G_W1L : G_W0L);
        char* nxtA_h = gsm + ((it16 & 1) ? G_A0H : G_A1H);
        char* nxtA_l = gsm + ((it16 & 1) ? G_A0L : G_A1L);
        char* nxtW_h = gsm + ((it16 & 1) ? G_W0H : G_W1H);
        char* nxtW_l = gsm + ((it16 & 1) ? G_W0L : G_W1L);
        bool pf = (it16 + 1) < 16;
        float4 va, vw[4];
        if (pf) {
            int k0 = ks * 512 + (it16 + 1) * 32;
            va = *reinterpret_cast<const float4*>(A + ar * HID + k0 + ac);
#pragma unroll
            for (int itw = 0; itw < 4; itw++) {
                int i = itw * 256 + tid;
                vw[itw] = *reinterpret_cast<const float4*>(
                    W + (size_t)(n0 + (i >> 3)) * HID + k0 + ((i & 7) * 4));
            }
        }
#pragma unroll
        for (int kk = 0; kk < 2; kk++) {
            uint32_t ah[2][4], al[2][4];
#pragma unroll
            for (int mi = 0; mi < 2; mi++) {
                ldsm4(ah[mi], (const __nv_bfloat16*)curA_h + (mi * 16 + (lane & 15)) * 40 + kk * 16 + (lane >> 4) * 8);
                ldsm4(al[mi], (const __nv_bfloat16*)curA_l + (mi * 16 + (lane & 15)) * 40 + kk * 16 + (lane >> 4) * 8);
            }
            int brow = warp * 16 + ((lane >> 4) << 3) + (lane & 7);
            int bcol = kk * 16 + (((lane >> 3) & 1) << 3);
            uint32_t bh[4], bl[4];
            ldsm4(bh, (const __nv_bfloat16*)curW_h + brow * 40 + bcol);
            ldsm4(bl, (const __nv_bfloat16*)curW_l + brow * 40 + bcol);
#pragma unroll
            for (int nf = 0; nf < 2; nf++)
#pragma unroll
                for (int mi = 0; mi < 2; mi++)
                    mma16816(c[mi][nf], ah[mi], bh[nf * 2], bh[nf * 2 + 1]);
#pragma unroll
            for (int nf = 0; nf < 2; nf++)
#pragma unroll
                for (int mi = 0; mi < 2; mi++)
                    mma16816(c[mi][nf], ah[mi], bl[nf * 2], bl[nf * 2 + 1]);
#pragma unroll
            for (int nf = 0; nf < 2; nf++)
#pragma unroll
                for (int mi = 0; mi < 2; mi++)
                    mma16816(c[mi][nf], al[mi], bh[nf * 2], bh[nf * 2 + 1]);
        }
        if (pf) {
            split_store(va, (__nv_bfloat16*)nxtA_h + ar * 40 + ac,
                            (__nv_bfloat16*)nxtA_l + ar * 40 + ac);
#pragma unroll
            for (int itw = 0; itw < 4; itw++) {
                int i = itw * 256 + tid;
                int r = i >> 3, cc = (i & 7) * 4;
                split_store(vw[itw], (__nv_bfloat16*)nxtW_h + r * 40 + cc,
                                     (__nv_bfloat16*)nxtW_l + r * 40 + cc);
            }
        }
        __syncthreads();
    }
#pragma unroll
    for (int mi = 0; mi < 2; mi++)
#pragma unroll
        for (int nf = 0; nf < 2; nf++) {
            int row = mi * 16 + g;
            int col = n0 + warp * 16 + nf * 8 + 2 * t;
            float* o = g_part + ks * (B * HID) + (size_t)row * HID + col;
            *reinterpret_cast<float2*>(o) = make_float2(c[mi][nf][0], c[mi][nf][1]);
            *reinterpret_cast<float2*>(o + 8 * HID) = make_float2(c[mi][nf][2], c[mi][nf][3]);
        }
}

// ---------------- reduces
__global__ void reduce8_k(float* __restrict__ dst, const float* __restrict__ bias) {
    int i = blockIdx.x * 256 + threadIdx.x;
    float v = 0.f;
#pragma unroll
    for (int s = 0; s < 8; s++) v += g_part[s * 131072 + i];
    if (bias) v += bias[i & (HID - 1)];
    dst[i] = v;
}
__global__ void reduce4_k(float* __restrict__ dst, const float* __restrict__ bias) {
    int i = blockIdx.x * 256 + threadIdx.x;
    float v = g_part[i] + g_part[131072 + i] + g_part[2 * 131072 + i] + g_part[3 * 131072 + i];
    if (bias) v += bias[i & (HID - 1)];
    dst[i] = v;
}

// ---------------- q_absorbed
__global__ void qabsorb_k(const float* __restrict__ w_kc) {
    const int h = blockIdx.y;
    const int r0 = blockIdx.x * 128;
    __shared__ float As[32][33];
    __shared__ float Bs[32][132];
    const int tid = threadIdx.x;
    const int ty = tid / 32, tx = tid % 32;
    float acc[4][4] = {};
    for (int d0 = 0; d0 < 128; d0 += 32) {
        {
            int r = tid / 8, c = (tid % 8) * 4;
            float4 v = *reinterpret_cast<const float4*>(g_q + r * HID + h * D + d0 + c);
            As[r][c] = v.x; As[r][c + 1] = v.y; As[r][c + 2] = v.z; As[r][c + 3] = v.w;
        }
#pragma unroll
        for (int it = 0; it < 4; it++) {
            int i = tid + it * 256;
            int rr = i / 32, c = (i % 32) * 4;
            float4 v = *reinterpret_cast<const float4*>(w_kc + (size_t)(h * D + d0 + rr) * R + r0 + c);
            *reinterpret_cast<float4*>(&Bs[rr][c]) = v;
        }
        __syncthreads();
#pragma unroll
        for (int dd = 0; dd < 32; dd++) {
            float4 bv = *reinterpret_cast<float4*>(&Bs[dd][tx * 4]);
            float bb[4] = {bv.x, bv.y, bv.z, bv.w};
#pragma unroll
            for (int i = 0; i < 4; i++) {
                float a = As[ty * 4 + i][dd];
#pragma unroll
                for (int j = 0; j < 4; j++) acc[i][j] += a * bb[j];
            }
        }
        __syncthreads();
    }
#pragma unroll
    for (int i = 0; i < 4; i++)
#pragma unroll
        for (int j = 0; j < 4; j++)
            g_qa[((ty * 4 + i) * H + h) * R + r0 + tx * 4 + j] = acc[i][j];
}

// ---------------- fused flash MLA: 512 threads, split accumulators, low reg pressure ----------------
#define AST 520
#define PST 40
#define SRST 34
#define OFF_AH 0
#define OFF_AL 33280
#define OFF_V0H 66560
#define OFF_V0L 99840
#define OFF_V1H 133120
#define OFF_V1L 166400
#define OFF_PH 199680
#define OFF_PL 202240
#define OFF_SRED 204800
#define OFF_WMAX 217856
#define OFF_WSUM 218112
#define OFF_MROW 218368
#define OFF_LROW 218496
#define SMEM_FMLA 218624

__global__ void __launch_bounds__(512, 1) fmla_k(const float* __restrict__ ckv) {
    extern __shared__ char smbuf[];
    __nv_bfloat16* Ah = reinterpret_cast<__nv_bfloat16*>(smbuf + OFF_AH);
    __nv_bfloat16* Al = reinterpret_cast<__nv_bfloat16*>(smbuf + OFF_AL);
    __nv_bfloat16* Ph = reinterpret_cast<__nv_bfloat16*>(smbuf + OFF_PH);
    __nv_bfloat16* Pl = reinterpret_cast<__nv_bfloat16*>(smbuf + OFF_PL);
    float* Sred = reinterpret_cast<float*>(smbuf + OFF_SRED);
    float* wmax = reinterpret_cast<float*>(smbuf + OFF_WMAX);
    float* wsum = reinterpret_cast<float*>(smbuf + OFF_WSUM);
    float* mrow = reinterpret_cast<float*>(smbuf + OFF_MROW);
    float* lrow = reinterpret_cast<float*>(smbuf + OFF_LROW);

    const int sp = blockIdx.x, b = blockIdx.y;
    const int tid = threadIdx.x;
    const int warp = tid >> 5, lane = tid & 31;
    const int g = lane >> 2, t = lane & 3;
    const int kw = warp >> 2;
    const int mw = (warp >> 1) & 1;
    const int nw = warp & 1;

    // prologue: A and V(0)
#pragma unroll
    for (int it = 0; it < 8; it++) {
        int i = it * 512 + tid;
        int row = i >> 7, cc = (i & 127) * 4;
        float4 v = *reinterpret_cast<const float4*>(g_qa + (size_t)(b * H + row) * R + cc);
        split_store(v, &Ah[row * AST + cc], &Al[row * AST + cc]);
    }
    {
        const float4* src4 = reinterpret_cast<const float4*>(ckv + ((size_t)b * S + sp * SB) * R);
        __nv_bfloat16* Vh = reinterpret_cast<__nv_bfloat16*>(smbuf + OFF_V0H);
        __nv_bfloat16* Vl = reinterpret_cast<__nv_bfloat16*>(smbuf + OFF_V0L);
#pragma unroll
        for (int it = 0; it < 8; it++) {
            int i = it * 512 + tid;
            int row = i >> 7, cc = (i & 127) * 4;
            split_store(src4[i], &Vh[row * AST + cc], &Vl[row * AST + cc]);
        }
    }
    if (tid < 32) { mrow[tid] = -3e38f; lrow[tid] = 0.f; }
    __syncthreads();

    float cv[2][4][4] = {};

    for (int ii = 0; ii < NCHUNK; ii++) {
        __nv_bfloat16* Vqh = reinterpret_cast<__nv_bfloat16*>(smbuf + ((ii & 1) ? OFF_V1H : OFF_V0H));
        __nv_bfloat16* Vql = reinterpret_cast<__nv_bfloat16*>(smbuf + ((ii & 1) ? OFF_V1L : OFF_V0L));
        __nv_bfloat16* Vph = reinterpret_cast<__nv_bfloat16*>(smbuf + ((ii & 1) ? OFF_V0H : OFF_V1H));
        __nv_bfloat16* Vpl = reinterpret_cast<__nv_bfloat16*>(smbuf + ((ii & 1) ? OFF_V0L : OFF_V1L));
        const bool pf = (ii + 1) < NCHUNK;

        // running m/l update for chunk ii-1 (off critical path)
        if (tid < 32 && ii > 0) {
            float mo = mrow[tid];
            float cm = fmaxf(wmax[tid], wmax[32 + tid]);
            float mn = fmaxf(mo, cm);
            float a = __expf(mo - mn);
            lrow[tid] = lrow[tid] * a + wsum[tid] + wsum[32 + tid];
            mrow[tid] = mn;
        }

        const float4* src4 = reinterpret_cast<const float4*>(
            ckv + ((size_t)b * S + sp * SB + (ii + 1) * SC) * R);
        float4 pv[4];
        if (pf) {
#pragma unroll
            for (int j = 0; j < 4; j++) pv[j] = src4[j * 512 + tid];
        }

        // ---- PV for chunk ii-1 (term-outer order: acc reuse distance 4) ----
        if (ii > 0) {
#pragma unroll
            for (int kk = 0; kk < 2; kk++) {
                int k0 = kk * 16;
                uint32_t ph[2][4], pl[2][4];
#pragma unroll
                for (int mi = 0; mi < 2; mi++) {
                    ldsm4(ph[mi], &Ph[(mi * 16 + (lane & 15)) * PST + k0 + (lane >> 4) * 8]);
                    ldsm4(pl[mi], &Pl[(mi * 16 + (lane & 15)) * PST + k0 + (lane >> 4) * 8]);
                }
#pragma unroll
                for (int j2 = 0; j2 < 2; j2++) {
                    int vrow = k0 + (lane & 7) + (((lane >> 3) & 1) << 3);
                    int vcol = warp * 32 + j2 * 16 + (lane >> 4) * 8;
                    uint32_t vh[4], vl[4];
                    ldsm4t(vh, &Vph[vrow * AST + vcol]);
                    ldsm4t(vl, &Vpl[vrow * AST + vcol]);
#pragma unroll
                    for (int half = 0; half < 2; half++)
#pragma unroll
                        for (int mi = 0; mi < 2; mi++)
                            mma16816(cv[mi][j2 * 2 + half], ph[mi], vh[half * 2], vh[half * 2 + 1]);
#pragma unroll
                    for (int half = 0; half < 2; half++)
#pragma unroll
                        for (int mi = 0; mi < 2; mi++)
                            mma16816(cv[mi][j2 * 2 + half], ph[mi], vl[half * 2], vl[half * 2 + 1]);
#pragma unroll
                    for (int half = 0; half < 2; half++)
#pragma unroll
                        for (int mi = 0; mi < 2; mi++)
                            mma16816(cv[mi][j2 * 2 + half], pl[mi], vh[half * 2], vh[half * 2 + 1]);
                }
            }
        }
        __syncthreads();   // ---- sync D : Vp free ----

        // convert V(ii+1) first half; frees pv regs before QK
        if (pf) {
#pragma unroll
            for (int j = 0; j < 4; j++) {
                int i1 = j * 512 + tid;
                int row = i1 >> 7, cc = (i1 & 127) * 4;
                split_store(pv[j], &Vph[row * AST + cc], &Vpl[row * AST + cc]);
            }
#pragma unroll
            for (int j = 0; j < 4; j++) pv[j] = src4[(j + 4) * 512 + tid];
        }

        // ---- QK for chunk ii : 3 split accumulator sets ----
        float cqA[2][4] = {}, cqB[2][4] = {}, cqC[2][4] = {};
#pragma unroll
        for (int kk = 0; kk < 8; kk++) {
            int k0 = kw * 128 + kk * 16;
            uint32_t ah[4], al[4];
            ldsm4(ah, &Ah[(mw * 16 + (lane & 15)) * AST + k0 + (lane >> 4) * 8]);
            ldsm4(al, &Al[(mw * 16 + (lane & 15)) * AST + k0 + (lane >> 4) * 8]);
            int brow = nw * 16 + ((lane >> 4) << 3) + (lane & 7);
            int bcol = k0 + (((lane >> 3) & 1) << 3);
            uint32_t bh[4], bl[4];
            ldsm4(bh, &Vqh[brow * AST + bcol]);
            ldsm4(bl, &Vql[brow * AST + bcol]);
#pragma unroll
            for (int nf = 0; nf < 2; nf++) mma16816(cqA[nf], ah, bh[nf * 2], bh[nf * 2 + 1]);
#pragma unroll
            for (int nf = 0; nf < 2; nf++) mma16816(cqB[nf], ah, bl[nf * 2], bl[nf * 2 + 1]);
#pragma unroll
            for (int nf = 0; nf < 2; nf++) mma16816(cqC[nf], al, bh[nf * 2], bh[nf * 2 + 1]);
        }
        float cq[2][4];
#pragma unroll
        for (int nf = 0; nf < 2; nf++)
#pragma unroll
            for (int i2 = 0; i2 < 4; i2++)
                cq[nf][i2] = cqA[nf][i2] + cqB[nf][i2] + cqC[nf][i2];
        if (kw > 0) {
#pragma unroll
            for (int nf = 0; nf < 2; nf++) {
                int col = nw * 16 + nf * 8 + 2 * t;
                float* s0 = &Sred[(kw - 1) * 1088 + (mw * 16 + g) * SRST + col];
                *reinterpret_cast<float2*>(s0) = make_float2(cq[nf][0], cq[nf][1]);
                *reinterpret_cast<float2*>(s0 + 8 * SRST) = make_float2(cq[nf][2], cq[nf][3]);
            }
        }
        __syncthreads();   // ---- sync A ----

        // convert V(ii+1) second half (overlaps kw0 reduce)
        if (pf) {
#pragma unroll
            for (int j = 0; j < 4; j++) {
                int i1 = (j + 4) * 512 + tid;
                int row = i1 >> 7, cc = (i1 & 127) * 4;
                split_store(pv[j], &Vph[row * AST + cc], &Vpl[row * AST + cc]);
            }
        }
        // k-split reduce + row max (kw==0 warps)
        if (kw == 0) {
            float mA = -3e38f, mB = -3e38f;
#pragma unroll
            for (int nf = 0; nf < 2; nf++) {
                int col = nw * 16 + nf * 8 + 2 * t;
#pragma unroll
                for (int p = 0; p < 3; p++) {
                    float2 r0 = *reinterpret_cast<float2*>(&Sred[p * 1088 + (mw * 16 + g) * SRST + col]);
                    float2 r1 = *reinterpret_cast<float2*>(&Sred[p * 1088 + (mw * 16 + g + 8) * SRST + col]);
                    cq[nf][0] += r0.x; cq[nf][1] += r0.y;
                    cq[nf][2] += r1.x; cq[nf][3] += r1.y;
                }
                cq[nf][0] *= SCALE; cq[nf][1] *= SCALE;
                cq[nf][2] *= SCALE; cq[nf][3] *= SCALE;
                mA = fmaxf(mA, fmaxf(cq[nf][0], cq[nf][1]));
                mB = fmaxf(mB, fmaxf(cq[nf][2], cq[nf][3]));
            }
            mA = fmaxf(mA, __shfl_xor_sync(0xffffffffu, mA, 1));
            mA = fmaxf(mA, __shfl_xor_sync(0xffffffffu, mA, 2));
            mB = fmaxf(mB, __shfl_xor_sync(0xffffffffu, mB, 1));
            mB = fmaxf(mB, __shfl_xor_sync(0xffffffffu, mB, 2));
            if (t == 0) {
                wmax[nw * 32 + mw * 16 + g] = mA;
                wmax[nw * 32 + mw * 16 + g + 8] = mB;
            }
        }
        __syncthreads();   // ---- sync B ----

        // all warps: rescale cv by alpha(ii), computed locally
        {
            int rows[4] = {g, g + 8, 16 + g, 24 + g};
            float a_[4];
#pragma unroll
            for (int k = 0; k < 4; k++) {
                float mo = mrow[rows[k]];
                float cm = fmaxf(wmax[rows[k]], wmax[32 + rows[k]]);
                float mn = fmaxf(mo, cm);
                a_[k] = __expf(mo - mn);
            }
#pragma unroll
            for (int nj = 0; nj < 4; nj++) {
                cv[0][nj][0] *= a_[0]; cv[0][nj][1] *= a_[0];
                cv[0][nj][2] *= a_[1]; cv[0][nj][3] *= a_[1];
                cv[1][nj][0] *= a_[2]; cv[1][nj][1] *= a_[2];
                cv[1][nj][2] *= a_[3]; cv[1][nj][3] *= a_[3];
            }
        }
        // kw==0 warps: P = exp(s - m), write hi/lo + partial sums
        if (kw == 0) {
            int rA = mw * 16 + g;
            float mA = fmaxf(mrow[rA], fmaxf(wmax[rA], wmax[32 + rA]));
            float mB = fmaxf(mrow[rA + 8], fmaxf(wmax[rA + 8], wmax[32 + rA + 8]));
            float sA = 0.f, sB = 0.f;
#pragma unroll
            for (int nf = 0; nf < 2; nf++) {
                float p0 = __expf(cq[nf][0] - mA), p1 = __expf(cq[nf][1] - mA);
                float p2 = __expf(cq[nf][2] - mB), p3 = __expf(cq[nf][3] - mB);
                sA += p0 + p1; sB += p2 + p3;
                int col = nw * 16 + nf * 8 + 2 * t;
                __nv_bfloat16 h0 = __float2bfloat16(p0), h1 = __float2bfloat16(p1);
                __nv_bfloat16 h2 = __float2bfloat16(p2), h3 = __float2bfloat16(p3);
                *reinterpret_cast<uint32_t*>(&Ph[rA * PST + col]) = pack2(h0, h1);
                *reinterpret_cast<uint32_t*>(&Ph[(rA + 8) * PST + col]) = pack2(h2, h3);
                __nv_bfloat16 l0 = __float2bfloat16(p0 - __bfloat162float(h0));
                __nv_bfloat16 l1 = __float2bfloat16(p1 - __bfloat162float(h1));
                __nv_bfloat16 l2 = __float2bfloat16(p2 - __bfloat162float(h2));
                __nv_bfloat16 l3 = __float2bfloat16(p3 - __bfloat162float(h3));
                *reinterpret_cast<uint32_t*>(&Pl[rA * PST + col]) = pack2(l0, l1);
                *reinterpret_cast<uint32_t*>(&Pl[(rA + 8) * PST + col]) = pack2(l2, l3);
            }
            sA += __shfl_xor_sync(0xffffffffu, sA, 1);
            sA += __shfl_xor_sync(0xffffffffu, sA, 2);
            sB += __shfl_xor_sync(0xffffffffu, sB, 1);
            sB += __shfl_xor_sync(0xffffffffu, sB, 2);
            if (t == 0) { wsum[nw * 32 + rA] = sA; wsum[nw * 32 + rA + 8] = sB; }
        }
        __syncthreads();   // ---- sync C ----
    }

    // epilogue: final m/l update + PV for last chunk
    if (tid < 32) {
        float mo = mrow[tid];
        float cm = fmaxf(wmax[tid], wmax[32 + tid]);
        float mn = fmaxf(mo, cm);
        float a = __expf(mo - mn);
        lrow[tid] = lrow[tid] * a + wsum[tid] + wsum[32 + tid];
        mrow[tid] = mn;
    }
    {
        __nv_bfloat16* Vph = reinterpret_cast<__nv_bfloat16*>(smbuf + ((NCHUNK & 1) ? OFF_V0H : OFF_V1H));
        __nv_bfloat16* Vpl = reinterpret_cast<__nv_bfloat16*>(smbuf + ((NCHUNK & 1) ? OFF_V0L : OFF_V1L));
#pragma unroll
        for (int kk = 0; kk < 2; kk++) {
            int k0 = kk * 16;
            uint32_t ph[2][4], pl[2][4];
#pragma unroll
            for (int mi = 0; mi < 2; mi++) {
                ldsm4(ph[mi], &Ph[(mi * 16 + (lane & 15)) * PST + k0 + (lane >> 4) * 8]);
                ldsm4(pl[mi], &Pl[(mi * 16 + (lane & 15)) * PST + k0 + (lane >> 4) * 8]);
            }
#pragma unroll
            for (int j2 = 0; j2 < 2; j2++) {
                int vrow = k0 + (lane & 7) + (((lane >> 3) & 1) << 3);
                int vcol = warp * 32 + j2 * 16 + (lane >> 4) * 8;
                uint32_t vh[4], vl[4];
                ldsm4t(vh, &Vph[vrow * AST + vcol]);
                ldsm4t(vl, &Vpl[vrow * AST + vcol]);
#pragma unroll
                for (int half = 0; half < 2; half++)
#pragma unroll
                    for (int mi = 0; mi < 2; mi++)
                        mma16816(cv[mi][j2 * 2 + half], ph[mi], vh[half * 2], vh[half * 2 + 1]);
#pragma unroll
                for (int half = 0; half < 2; half++)
#pragma unroll
                    for (int mi = 0; mi < 2; mi++)
                        mma16816(cv[mi][j2 * 2 + half], ph[mi], vl[half * 2], vl[half * 2 + 1]);
#pragma unroll
                for (int half = 0; half < 2; half++)
#pragma unroll
                    for (int mi = 0; mi < 2; mi++)
                        mma16816(cv[mi][j2 * 2 + half], pl[mi], vh[half * 2], vh[half * 2 + 1]);
            }
        }
    }
    if (tid < 32) {
        g_m[(sp * B + b) * H + tid] = mrow[tid];
        g_l[(sp * B + b) * H + tid] = lrow[tid];
    }
#pragma unroll
    for (int mi = 0; mi < 2; mi++)
#pragma unroll
        for (int nj = 0; nj < 4; nj++) {
            int row = mi * 16 + g;
            int col = warp * 32 + nj * 8 + 2 * t;
            float* o = g_ctxp + ((size_t)(sp * B + b) * H + row) * R + col;
            *reinterpret_cast<float2*>(o) = make_float2(cv[mi][nj][0], cv[mi][nj][1]);
            *reinterpret_cast<float2*>(o + 8 * R) = make_float2(cv[mi][nj][2], cv[mi][nj][3]);
        }
}

// ---------------- combine ----------------
__global__ void combine_k() {
    int bh = blockIdx.x;
    __shared__ float w[NSPLIT];
    __shared__ float invL;
    if (threadIdx.x == 0) {
        float M = -3e38f;
#pragma unroll
        for (int sp = 0; sp < NSPLIT; sp++) M = fmaxf(M, g_m[sp * (B * H) + bh]);
        float L = 0.f;
#pragma unroll
        for (int sp = 0; sp < NSPLIT; sp++) {
            float ww = __expf(g_m[sp * (B * H) + bh] - M);
            w[sp] = ww;
            L += ww * g_l[sp * (B * H) + bh];
        }
        invL = 1.f / L;
    }
    __syncthreads();
    for (int r = threadIdx.x; r < R; r += blockDim.x) {
        float acc = 0.f;
#pragma unroll
        for (int sp = 0; sp < NSPLIT; sp++)
            acc += w[sp] * g_ctxp[((size_t)sp * (B * H) + bh) * R + r];
        g_ctx[(size_t)bh * R + r] = acc * invL;
    }
}

// ---------------- vabsorb ----------------
__global__ void vabsorb_k(const float* __restrict__ w_vc) {
    const int h = blockIdx.y;
    const int ks = blockIdx.x;
    __shared__ float As[32][33];
    __shared__ float Bs[32][132];
    const int tid = threadIdx.x;
    const int ty = tid / 32, tx = tid % 32;
    float acc[4][4] = {};
    for (int r0 = ks * 128; r0 < ks * 128 + 128; r0 += 32) {
        {
            int r = tid / 8, c = (tid % 8) * 4;
            float4 v = *reinterpret_cast<const float4*>(g_ctx + (size_t)(r * H + h) * R + r0 + c);
            As[r][c] = v.x; As[r][c + 1] = v.y; As[r][c + 2] = v.z; As[r][c + 3] = v.w;
        }
#pragma unroll
        for (int it = 0; it < 4; it++) {
            int i = tid + it * 256;
            int rr = i / 32, c = (i % 32) * 4;
            float4 v = *reinterpret_cast<const float4*>(w_vc + (size_t)(h * R + r0 + rr) * D + c);
            *reinterpret_cast<float4*>(&Bs[rr][c]) = v;
        }
        __syncthreads();
#pragma unroll
        for (int dd = 0; dd < 32; dd++) {
            float4 bv = *reinterpret_cast<float4*>(&Bs[dd][tx * 4]);
            float bb[4] = {bv.x, bv.y, bv.z, bv.w};
#pragma unroll
            for (int i = 0; i < 4; i++) {
                float a = As[ty * 4 + i][dd];
#pragma unroll
                for (int j = 0; j < 4; j++) acc[i][j] += a * bb[j];
            }
        }
        __syncthreads();
    }
#pragma unroll
    for (int i = 0; i < 4; i++)
#pragma unroll
        for (int j = 0; j < 4; j++)
            g_part[(ks * B + ty * 4 + i) * HID + h * D + tx * 4 + j] = acc[i][j];
}

// ---------------- launch ----------------
extern "C" void kernel_launch(void* const* d_in, const int* in_sizes, int n_in,
                              void* d_out, int out_size) {
    const float* hs   = (const float*)d_in[0];
    const float* ckv  = (const float*)d_in[1];
    const float* q_w  = (const float*)d_in[2];
    const float* q_b  = (const float*)d_in[3];
    const float* w_kc = (const float*)d_in[4];
    const float* w_vc = (const float*)d_in[5];
    const float* o_w  = (const float*)d_in[6];
    const float* o_b  = (const float*)d_in[7];
    float* out = (float*)d_out;

    float *pq, *pattn;
    cudaGetSymbolAddress((void**)&pq, g_q);
    cudaGetSymbolAddress((void**)&pattn, g_attn);
    cudaFuncSetAttribute(fmla_k, cudaFuncAttributeMaxDynamicSharedMemorySize, SMEM_FMLA);
    cudaFuncSetAttribute(gemm_bf_k, cudaFuncAttributeMaxDynamicSharedMemorySize, SMEM_GEMM);

    gemm_bf_k<<<dim3(32, 8), 256, SMEM_GEMM>>>(hs, q_w);
    reduce8_k<<<512, 256>>>(pq, q_b);
    qabsorb_k<<<dim3(4, 32), 256>>>(w_kc);
    fmla_k<<<dim3(NSPLIT, B), 512, SMEM_FMLA>>>(ckv);
    combine_k<<<B * H, 128>>>();
    vabsorb_k<<<dim3(4, 32), 256>>>(w_vc);
    reduce4_k<<<512, 256>>>(pattn, nullptr);
    gemm_bf_k<<<dim3(32, 8), 256, SMEM_GEMM>>>(pattn, o_w);
    reduce8_k<<<512, 256>>>(out, o_b);
}

// round 15
// speedup vs baseline: 1.2196x; 1.2098x over previous
#include <cuda_runtime.h>
#include <cuda_bf16.h>
#include <cuda_fp16.h>
#include <cstdint>

#define B 32
#define H 32
#define D 128
#define R 512
#define S 4096
#define HID 4096
#define SCALE 0.08838834764831845f
#define NSPLIT 4
#define SB (S / NSPLIT)
#define SC 32
#define NCHUNK (SB / SC)

// ---------------- scratch ----------------
__device__ float g_q[B * HID];
__device__ float g_part[8 * B * HID];
__device__ float g_qa[B * H * R];
__device__ float g_ctx[B * H * R];
__device__ float g_attn[B * HID];
__device__ float g_ctxp[8 * B * H * R];
__device__ float g_m[8 * B * H];
__device__ float g_l[8 * B * H];

// ---------------- helpers ----------------
__device__ __forceinline__ uint32_t pack2(__nv_bfloat16 a, __nv_bfloat16 b) {
    return (uint32_t)__bfloat16_as_ushort(a) | ((uint32_t)__bfloat16_as_ushort(b) << 16);
}
__device__ __forceinline__ uint32_t pack2h(__half a, __half b) {
    return (uint32_t)__half_as_ushort(a) | ((uint32_t)__half_as_ushort(b) << 16);
}
// bf16 hi/lo split (projections)
__device__ __forceinline__ void split_store(float4 v, __nv_bfloat16* hp, __nv_bfloat16* lp) {
    __nv_bfloat16 h0 = __float2bfloat16(v.x), h1 = __float2bfloat16(v.y),
                  h2 = __float2bfloat16(v.z), h3 = __float2bfloat16(v.w);
    __nv_bfloat16 l0 = __float2bfloat16(v.x - __bfloat162float(h0));
    __nv_bfloat16 l1 = __float2bfloat16(v.y - __bfloat162float(h1));
    __nv_bfloat16 l2 = __float2bfloat16(v.z - __bfloat162float(h2));
    __nv_bfloat16 l3 = __float2bfloat16(v.w - __bfloat162float(h3));
    *reinterpret_cast<uint2*>(hp) = make_uint2(pack2(h0, h1), pack2(h2, h3));
    *reinterpret_cast<uint2*>(lp) = make_uint2(pack2(l0, l1), pack2(l2, l3));
}
// fp16 hi/lo split (qa in fmla)
__device__ __forceinline__ void split_store_h(float4 v, __half* hp, __half* lp) {
    __half h0 = __float2half(v.x), h1 = __float2half(v.y),
           h2 = __float2half(v.z), h3 = __float2half(v.w);
    __half l0 = __float2half(v.x - __half2float(h0));
    __half l1 = __float2half(v.y - __half2float(h1));
    __half l2 = __float2half(v.z - __half2float(h2));
    __half l3 = __float2half(v.w - __half2float(h3));
    *reinterpret_cast<uint2*>(hp) = make_uint2(pack2h(h0, h1), pack2h(h2, h3));
    *reinterpret_cast<uint2*>(lp) = make_uint2(pack2h(l0, l1), pack2h(l2, l3));
}
// fp16 single store (V in fmla)
__device__ __forceinline__ void store_h4(float4 v, __half* hp) {
    *reinterpret_cast<uint2*>(hp) = make_uint2(
        pack2h(__float2half(v.x), __float2half(v.y)),
        pack2h(__float2half(v.z), __float2half(v.w)));
}
__device__ __forceinline__ uint32_t saddr(const void* p) {
    return (uint32_t)__cvta_generic_to_shared(p);
}
__device__ __forceinline__ void ldsm4(uint32_t* r, const void* p) {
    asm volatile("ldmatrix.sync.aligned.m8n8.x4.shared.b16 {%0,%1,%2,%3},[%4];\n"
                 : "=r"(r[0]), "=r"(r[1]), "=r"(r[2]), "=r"(r[3]) : "r"(saddr(p)));
}
__device__ __forceinline__ void ldsm4t(uint32_t* r, const void* p) {
    asm volatile("ldmatrix.sync.aligned.m8n8.x4.trans.shared.b16 {%0,%1,%2,%3},[%4];\n"
                 : "=r"(r[0]), "=r"(r[1]), "=r"(r[2]), "=r"(r[3]) : "r"(saddr(p)));
}
// bf16 mma (projections)
__device__ __forceinline__ void mma16816(float* c, const uint32_t* a, uint32_t b0, uint32_t b1) {
    asm volatile(
        "mma.sync.aligned.m16n8k16.row.col.f32.bf16.bf16.f32 "
        "{%0,%1,%2,%3},{%4,%5,%6,%7},{%8,%9},{%0,%1,%2,%3};\n"
        : "+f"(c[0]), "+f"(c[1]), "+f"(c[2]), "+f"(c[3])
        : "r"(a[0]), "r"(a[1]), "r"(a[2]), "r"(a[3]), "r"(b0), "r"(b1));
}
// fp16 mma (fmla)
__device__ __forceinline__ void mma16816h(float* c, const uint32_t* a, uint32_t b0, uint32_t b1) {
    asm volatile(
        "mma.sync.aligned.m16n8k16.row.col.f32.f16.f16.f32 "
        "{%0,%1,%2,%3},{%4,%5,%6,%7},{%8,%9},{%0,%1,%2,%3};\n"
        : "+f"(c[0]), "+f"(c[1]), "+f"(c[2]), "+f"(c[3])
        : "r"(a[0]), "r"(a[1]), "r"(a[2]), "r"(a[3]), "r"(b0), "r"(b1));
}

// ---------------- bf16 hi/lo GEMM-NT, split-K 8, double-buffered smem
#define GA 2560
#define GW 10240
#define G_A0H 0
#define G_A0L (GA)
#define G_A1H (2*GA)
#define G_A1L (3*GA)
#define G_W0H (4*GA)
#define G_W0L (4*GA + GW)
#define G_W1H (4*GA + 2*GW)
#define G_W1L (4*GA + 3*GW)
#define SMEM_GEMM (4*GA + 4*GW)

__global__ void __launch_bounds__(256) gemm_bf_k(const float* __restrict__ A,
                                                 const float* __restrict__ W) {
    extern __shared__ char gsm[];
    const int n0 = blockIdx.x * 128;
    const int ks = blockIdx.y;
    const int tid = threadIdx.x;
    const int warp = tid >> 5, lane = tid & 31;
    const int g = lane >> 2, t = lane & 3;
    float c[2][2][4] = {};

    const int ar = tid >> 3, ac = (tid & 7) * 4;
    {
        int k0 = ks * 512;
        float4 va = *reinterpret_cast<const float4*>(A + ar * HID + k0 + ac);
        split_store(va, (__nv_bfloat16*)(gsm + G_A0H) + ar * 40 + ac,
                        (__nv_bfloat16*)(gsm + G_A0L) + ar * 40 + ac);
#pragma unroll
        for (int it = 0; it < 4; it++) {
            int i = it * 256 + tid;
            int r = i >> 3, cc = (i & 7) * 4;
            float4 v = *reinterpret_cast<const float4*>(W + (size_t)(n0 + r) * HID + k0 + cc);
            split_store(v, (__nv_bfloat16*)(gsm + G_W0H) + r * 40 + cc,
                           (__nv_bfloat16*)(gsm + G_W0L) + r * 40 + cc);
        }
    }
    __syncthreads();

    for (int it16 = 0; it16 < 16; it16++) {
        const char* curA_h = gsm + ((it16 & 1) ? G_A1H : G_A0H);
        const char* curA_l = gsm + ((it16 & 1) ? G_A1L : G_A0L);
        const char* curW_h = gsm + ((it16 & 1) ? G_W1H : G_W0H);
        const char* curW_l = gsm + ((it16 & 1) ? G_W1L : G_W0L);
        char* nxtA_h = gsm + ((it16 & 1) ? G_A0H : G_A1H);
        char* nxtA_l = gsm + ((it16 & 1) ? G_A0L : G_A1L);
        char* nxtW_h = gsm + ((it16 & 1) ? G_W0H : G_W1H);
        char* nxtW_l = gsm + ((it16 & 1) ? G_W0L : G_W1L);
        bool pf = (it16 + 1) < 16;
        float4 va, vw[4];
        if (pf) {
            int k0 = ks * 512 + (it16 + 1) * 32;
            va = *reinterpret_cast<const float4*>(A + ar * HID + k0 + ac);
#pragma unroll
            for (int itw = 0; itw < 4; itw++) {
                int i = itw * 256 + tid;
                vw[itw] = *reinterpret_cast<const float4*>(
                    W + (size_t)(n0 + (i >> 3)) * HID + k0 + ((i & 7) * 4));
            }
        }
#pragma unroll
        for (int kk = 0; kk < 2; kk++) {
            uint32_t ah[2][4], al[2][4];
#pragma unroll
            for (int mi = 0; mi < 2; mi++) {
                ldsm4(ah[mi], (const __nv_bfloat16*)curA_h + (mi * 16 + (lane & 15)) * 40 + kk * 16 + (lane >> 4) * 8);
                ldsm4(al[mi], (const __nv_bfloat16*)curA_l + (mi * 16 + (lane & 15)) * 40 + kk * 16 + (lane >> 4) * 8);
            }
            int brow = warp * 16 + ((lane >> 4) << 3) + (lane & 7);
            int bcol = kk * 16 + (((lane >> 3) & 1) << 3);
            uint32_t bh[4], bl[4];
            ldsm4(bh, (const __nv_bfloat16*)curW_h + brow * 40 + bcol);
            ldsm4(bl, (const __nv_bfloat16*)curW_l + brow * 40 + bcol);
#pragma unroll
            for (int nf = 0; nf < 2; nf++)
#pragma unroll
                for (int mi = 0; mi < 2; mi++)
                    mma16816(c[mi][nf], ah[mi], bh[nf * 2], bh[nf * 2 + 1]);
#pragma unroll
            for (int nf = 0; nf < 2; nf++)
#pragma unroll
                for (int mi = 0; mi < 2; mi++)
                    mma16816(c[mi][nf], ah[mi], bl[nf * 2], bl[nf * 2 + 1]);
#pragma unroll
            for (int nf = 0; nf < 2; nf++)
#pragma unroll
                for (int mi = 0; mi < 2; mi++)
                    mma16816(c[mi][nf], al[mi], bh[nf * 2], bh[nf * 2 + 1]);
        }
        if (pf) {
            split_store(va, (__nv_bfloat16*)nxtA_h + ar * 40 + ac,
                            (__nv_bfloat16*)nxtA_l + ar * 40 + ac);
#pragma unroll
            for (int itw = 0; itw < 4; itw++) {
                int i = itw * 256 + tid;
                int r = i >> 3, cc = (i & 7) * 4;
                split_store(vw[itw], (__nv_bfloat16*)nxtW_h + r * 40 + cc,
                                     (__nv_bfloat16*)nxtW_l + r * 40 + cc);
            }
        }
        __syncthreads();
    }
#pragma unroll
    for (int mi = 0; mi < 2; mi++)
#pragma unroll
        for (int nf = 0; nf < 2; nf++) {
            int row = mi * 16 + g;
            int col = n0 + warp * 16 + nf * 8 + 2 * t;
            float* o = g_part + ks * (B * HID) + (size_t)row * HID + col;
            *reinterpret_cast<float2*>(o) = make_float2(c[mi][nf][0], c[mi][nf][1]);
            *reinterpret_cast<float2*>(o + 8 * HID) = make_float2(c[mi][nf][2], c[mi][nf][3]);
        }
}

// ---------------- reduces
__global__ void reduce8_k(float* __restrict__ dst, const float* __restrict__ bias) {
    int i = blockIdx.x * 256 + threadIdx.x;
    float v = 0.f;
#pragma unroll
    for (int s = 0; s < 8; s++) v += g_part[s * 131072 + i];
    if (bias) v += bias[i & (HID - 1)];
    dst[i] = v;
}
__global__ void reduce4_k(float* __restrict__ dst, const float* __restrict__ bias) {
    int i = blockIdx.x * 256 + threadIdx.x;
    float v = g_part[i] + g_part[131072 + i] + g_part[2 * 131072 + i] + g_part[3 * 131072 + i];
    if (bias) v += bias[i & (HID - 1)];
    dst[i] = v;
}

// ---------------- q_absorbed
__global__ void qabsorb_k(const float* __restrict__ w_kc) {
    const int h = blockIdx.y;
    const int r0 = blockIdx.x * 128;
    __shared__ float As[32][33];
    __shared__ float Bs[32][132];
    const int tid = threadIdx.x;
    const int ty = tid / 32, tx = tid % 32;
    float acc[4][4] = {};
    for (int d0 = 0; d0 < 128; d0 += 32) {
        {
            int r = tid / 8, c = (tid % 8) * 4;
            float4 v = *reinterpret_cast<const float4*>(g_q + r * HID + h * D + d0 + c);
            As[r][c] = v.x; As[r][c + 1] = v.y; As[r][c + 2] = v.z; As[r][c + 3] = v.w;
        }
#pragma unroll
        for (int it = 0; it < 4; it++) {
            int i = tid + it * 256;
            int rr = i / 32, c = (i % 32) * 4;
            float4 v = *reinterpret_cast<const float4*>(w_kc + (size_t)(h * D + d0 + rr) * R + r0 + c);
            *reinterpret_cast<float4*>(&Bs[rr][c]) = v;
        }
        __syncthreads();
#pragma unroll
        for (int dd = 0; dd < 32; dd++) {
            float4 bv = *reinterpret_cast<float4*>(&Bs[dd][tx * 4]);
            float bb[4] = {bv.x, bv.y, bv.z, bv.w};
#pragma unroll
            for (int i = 0; i < 4; i++) {
                float a = As[ty * 4 + i][dd];
#pragma unroll
                for (int j = 0; j < 4; j++) acc[i][j] += a * bb[j];
            }
        }
        __syncthreads();
    }
#pragma unroll
    for (int i = 0; i < 4; i++)
#pragma unroll
        for (int j = 0; j < 4; j++)
            g_qa[((ty * 4 + i) * H + h) * R + r0 + tx * 4 + j] = acc[i][j];
}

// ---------------- fused flash MLA: fp16 reduced-term, 512 threads, double-buffered V ----------------
// A (qa): fp16 hi/lo. V: fp16 single. QK = ah*vh + al*vh. P: fp16 hi/lo. PV = ph*vh + pl*vh.
#define AST 520
#define PST 40
#define SRST 34
#define OFF_AH 0
#define OFF_AL 33280
#define OFF_V0 66560
#define OFF_V1 99840
#define OFF_PH 133120
#define OFF_PL 135680
#define OFF_SRED 138240      /* 3 x 32 x 34 floats = 13056 */
#define OFF_WMAX 151296      /* 64 floats */
#define OFF_WSUM 151552      /* 64 floats */
#define OFF_MROW 151808      /* 32 floats */
#define OFF_LROW 151936      /* 32 floats */
#define OFF_ALPHA 152064     /* 32 floats — DEDICATED (was aliasing wsum in R13) */
#define SMEM_FMLA 152192

__global__ void __launch_bounds__(512, 1) fmla_k(const float* __restrict__ ckv) {
    extern __shared__ char smbuf[];
    __half* Ah = reinterpret_cast<__half*>(smbuf + OFF_AH);
    __half* Al = reinterpret_cast<__half*>(smbuf + OFF_AL);
    __half* Ph = reinterpret_cast<__half*>(smbuf + OFF_PH);
    __half* Pl = reinterpret_cast<__half*>(smbuf + OFF_PL);
    float* Sred = reinterpret_cast<float*>(smbuf + OFF_SRED);
    float* wmax = reinterpret_cast<float*>(smbuf + OFF_WMAX);
    float* wsum = reinterpret_cast<float*>(smbuf + OFF_WSUM);
    float* mrow = reinterpret_cast<float*>(smbuf + OFF_MROW);
    float* lrow = reinterpret_cast<float*>(smbuf + OFF_LROW);
    float* salpha = reinterpret_cast<float*>(smbuf + OFF_ALPHA);

    const int sp = blockIdx.x, b = blockIdx.y;
    const int tid = threadIdx.x;
    const int warp = tid >> 5, lane = tid & 31;
    const int g = lane >> 2, t = lane & 3;
    const int kw = warp >> 2;            // 4-way k split over r
    const int mw = (warp >> 1) & 1;      // m half (heads)
    const int nw = warp & 1;             // n half (s)

    // prologue: A (fp16 hi/lo) and V(0) (fp16)
#pragma unroll
    for (int it = 0; it < 8; it++) {
        int i = it * 512 + tid;
        int row = i >> 7, cc = (i & 127) * 4;
        float4 v = *reinterpret_cast<const float4*>(g_qa + (size_t)(b * H + row) * R + cc);
        split_store_h(v, &Ah[row * AST + cc], &Al[row * AST + cc]);
    }
    {
        const float4* src4 = reinterpret_cast<const float4*>(ckv + ((size_t)b * S + sp * SB) * R);
        __half* Vh = reinterpret_cast<__half*>(smbuf + OFF_V0);
#pragma unroll
        for (int it = 0; it < 8; it++) {
            int i = it * 512 + tid;
            int row = i >> 7, cc = (i & 127) * 4;
            store_h4(src4[i], &Vh[row * AST + cc]);
        }
    }
    if (tid < 32) { mrow[tid] = -3e38f; lrow[tid] = 0.f; }
    __syncthreads();

    float cv[2][4][4] = {};

    for (int ch = 0; ch < NCHUNK; ch++) {
        const __half* Vc = reinterpret_cast<const __half*>(smbuf + ((ch & 1) ? OFF_V1 : OFF_V0));
        __half* Vn = reinterpret_cast<__half*>(smbuf + ((ch & 1) ? OFF_V0 : OFF_V1));
        const bool pf = (ch + 1) < NCHUNK;
        const float4* src4 = reinterpret_cast<const float4*>(
            ckv + ((size_t)b * S + sp * SB + (ch + 1) * SC) * R);

        float cq[2][4] = {};
        float4 pv[4];
        if (pf) {
#pragma unroll
            for (int j = 0; j < 4; j++) pv[j] = src4[j * 512 + tid];
        }
        // ---- QK part 1 (kk 0..3): 2 fp16 terms ----
#pragma unroll
        for (int kk = 0; kk < 4; kk++) {
            int k0 = kw * 128 + kk * 16;
            uint32_t ah[4], al[4];
            ldsm4(ah, &Ah[(mw * 16 + (lane & 15)) * AST + k0 + (lane >> 4) * 8]);
            ldsm4(al, &Al[(mw * 16 + (lane & 15)) * AST + k0 + (lane >> 4) * 8]);
            int brow = nw * 16 + ((lane >> 4) << 3) + (lane & 7);
            int bcol = k0 + (((lane >> 3) & 1) << 3);
            uint32_t bh[4];
            ldsm4(bh, &Vc[brow * AST + bcol]);
#pragma unroll
            for (int nf = 0; nf < 2; nf++) mma16816h(cq[nf], ah, bh[nf * 2], bh[nf * 2 + 1]);
#pragma unroll
            for (int nf = 0; nf < 2; nf++) mma16816h(cq[nf], al, bh[nf * 2], bh[nf * 2 + 1]);
        }
        if (pf) {
#pragma unroll
            for (int j = 0; j < 4; j++) {
                int i = j * 512 + tid;
                int row = i >> 7, cc = (i & 127) * 4;
                store_h4(pv[j], &Vn[row * AST + cc]);
            }
#pragma unroll
            for (int j = 0; j < 4; j++) pv[j] = src4[(j + 4) * 512 + tid];
        }
        // ---- QK part 2 (kk 4..7) ----
#pragma unroll
        for (int kk = 4; kk < 8; kk++) {
            int k0 = kw * 128 + kk * 16;
            uint32_t ah[4], al[4];
            ldsm4(ah, &Ah[(mw * 16 + (lane & 15)) * AST + k0 + (lane >> 4) * 8]);
            ldsm4(al, &Al[(mw * 16 + (lane & 15)) * AST + k0 + (lane >> 4) * 8]);
            int brow = nw * 16 + ((lane >> 4) << 3) + (lane & 7);
            int bcol = k0 + (((lane >> 3) & 1) << 3);
            uint32_t bh[4];
            ldsm4(bh, &Vc[brow * AST + bcol]);
#pragma unroll
            for (int nf = 0; nf < 2; nf++) mma16816h(cq[nf], ah, bh[nf * 2], bh[nf * 2 + 1]);
#pragma unroll
            for (int nf = 0; nf < 2; nf++) mma16816h(cq[nf], al, bh[nf * 2], bh[nf * 2 + 1]);
        }
        if (pf) {
#pragma unroll
            for (int j = 0; j < 4; j++) {
                int i = (j + 4) * 512 + tid;
                int row = i >> 7, cc = (i & 127) * 4;
                store_h4(pv[j], &Vn[row * AST + cc]);
            }
        }
        // ---- k-split reduction + online softmax ----
        if (kw > 0) {
#pragma unroll
            for (int nf = 0; nf < 2; nf++) {
                int col = nw * 16 + nf * 8 + 2 * t;
                float* s0 = &Sred[(kw - 1) * 1088 + (mw * 16 + g) * SRST + col];
                *reinterpret_cast<float2*>(s0) = make_float2(cq[nf][0], cq[nf][1]);
                *reinterpret_cast<float2*>(s0 + 8 * SRST) = make_float2(cq[nf][2], cq[nf][3]);
            }
        }
        __syncthreads();
        if (kw == 0) {
            float mA = -3e38f, mB = -3e38f;
#pragma unroll
            for (int nf = 0; nf < 2; nf++) {
                int col = nw * 16 + nf * 8 + 2 * t;
#pragma unroll
                for (int p = 0; p < 3; p++) {
                    float2 r0 = *reinterpret_cast<float2*>(&Sred[p * 1088 + (mw * 16 + g) * SRST + col]);
                    float2 r1 = *reinterpret_cast<float2*>(&Sred[p * 1088 + (mw * 16 + g + 8) * SRST + col]);
                    cq[nf][0] += r0.x; cq[nf][1] += r0.y;
                    cq[nf][2] += r1.x; cq[nf][3] += r1.y;
                }
                cq[nf][0] *= SCALE; cq[nf][1] *= SCALE;
                cq[nf][2] *= SCALE; cq[nf][3] *= SCALE;
                mA = fmaxf(mA, fmaxf(cq[nf][0], cq[nf][1]));
                mB = fmaxf(mB, fmaxf(cq[nf][2], cq[nf][3]));
            }
            mA = fmaxf(mA, __shfl_xor_sync(0xffffffffu, mA, 1));
            mA = fmaxf(mA, __shfl_xor_sync(0xffffffffu, mA, 2));
            mB = fmaxf(mB, __shfl_xor_sync(0xffffffffu, mB, 1));
            mB = fmaxf(mB, __shfl_xor_sync(0xffffffffu, mB, 2));
            if (t == 0) {
                wmax[nw * 32 + mw * 16 + g] = mA;
                wmax[nw * 32 + mw * 16 + g + 8] = mB;
            }
        }
        __syncthreads();
        if (tid < 32) {
            float cm = fmaxf(wmax[tid], wmax[32 + tid]);
            float mo = mrow[tid];
            float mn = fmaxf(mo, cm);
            salpha[tid] = __expf(mo - mn);
            mrow[tid] = mn;
        }
        __syncthreads();
        {
#pragma unroll
            for (int mi = 0; mi < 2; mi++) {
                float rA = salpha[mi * 16 + g], rB = salpha[mi * 16 + g + 8];
#pragma unroll
                for (int nj = 0; nj < 4; nj++) {
                    cv[mi][nj][0] *= rA; cv[mi][nj][1] *= rA;
                    cv[mi][nj][2] *= rB; cv[mi][nj][3] *= rB;
                }
            }
        }
        if (kw == 0) {
            int rA = mw * 16 + g;
            float mA = mrow[rA], mB = mrow[rA + 8];
            float sA = 0.f, sB = 0.f;
#pragma unroll
            for (int nf = 0; nf < 2; nf++) {
                float p0 = __expf(cq[nf][0] - mA), p1 = __expf(cq[nf][1] - mA);
                float p2 = __expf(cq[nf][2] - mB), p3 = __expf(cq[nf][3] - mB);
                sA += p0 + p1; sB += p2 + p3;
                int col = nw * 16 + nf * 8 + 2 * t;
                __half h0 = __float2half(p0), h1 = __float2half(p1);
                __half h2 = __float2half(p2), h3 = __float2half(p3);
                *reinterpret_cast<uint32_t*>(&Ph[rA * PST + col]) = pack2h(h0, h1);
                *reinterpret_cast<uint32_t*>(&Ph[(rA + 8) * PST + col]) = pack2h(h2, h3);
                __half l0 = __float2half(p0 - __half2float(h0));
                __half l1 = __float2half(p1 - __half2float(h1));
                __half l2 = __float2half(p2 - __half2float(h2));
                __half l3 = __float2half(p3 - __half2float(h3));
                *reinterpret_cast<uint32_t*>(&Pl[rA * PST + col]) = pack2h(l0, l1);
                *reinterpret_cast<uint32_t*>(&Pl[(rA + 8) * PST + col]) = pack2h(l2, l3);
            }
            sA += __shfl_xor_sync(0xffffffffu, sA, 1);
            sA += __shfl_xor_sync(0xffffffffu, sA, 2);
            sB += __shfl_xor_sync(0xffffffffu, sB, 1);
            sB += __shfl_xor_sync(0xffffffffu, sB, 2);
            if (t == 0) { wsum[nw * 32 + rA] = sA; wsum[nw * 32 + rA + 8] = sB; }
        }
        __syncthreads();
        if (tid < 32) lrow[tid] = lrow[tid] * salpha[tid] + wsum[tid] + wsum[32 + tid];

        // ---- PV: ctx(32 x warp-n32) += (Ph + Pl)(32x32) @ V(32x512) ----
#pragma unroll
        for (int kk = 0; kk < 2; kk++) {
            int k0 = kk * 16;
            uint32_t ph[2][4], pl[2][4];
#pragma unroll
            for (int mi = 0; mi < 2; mi++) {
                ldsm4(ph[mi], &Ph[(mi * 16 + (lane & 15)) * PST + k0 + (lane >> 4) * 8]);
                ldsm4(pl[mi], &Pl[(mi * 16 + (lane & 15)) * PST + k0 + (lane >> 4) * 8]);
            }
#pragma unroll
            for (int j2 = 0; j2 < 2; j2++) {
                int vrow = k0 + (lane & 7) + (((lane >> 3) & 1) << 3);
                int vcol = warp * 32 + j2 * 16 + (lane >> 4) * 8;
                uint32_t vh[4];
                ldsm4t(vh, &Vc[vrow * AST + vcol]);
#pragma unroll
                for (int half = 0; half < 2; half++)
#pragma unroll
                    for (int mi = 0; mi < 2; mi++)
                        mma16816h(cv[mi][j2 * 2 + half], ph[mi], vh[half * 2], vh[half * 2 + 1]);
#pragma unroll
                for (int half = 0; half < 2; half++)
#pragma unroll
                    for (int mi = 0; mi < 2; mi++)
                        mma16816h(cv[mi][j2 * 2 + half], pl[mi], vh[half * 2], vh[half * 2 + 1]);
            }
        }
        __syncthreads();
    }
    if (tid < 32) {
        g_m[(sp * B + b) * H + tid] = mrow[tid];
        g_l[(sp * B + b) * H + tid] = lrow[tid];
    }
#pragma unroll
    for (int mi = 0; mi < 2; mi++)
#pragma unroll
        for (int nj = 0; nj < 4; nj++) {
            int row = mi * 16 + g;
            int col = warp * 32 + nj * 8 + 2 * t;
            float* o = g_ctxp + ((size_t)(sp * B + b) * H + row) * R + col;
            *reinterpret_cast<float2*>(o) = make_float2(cv[mi][nj][0], cv[mi][nj][1]);
            *reinterpret_cast<float2*>(o + 8 * R) = make_float2(cv[mi][nj][2], cv[mi][nj][3]);
        }
}

// ---------------- combine ----------------
__global__ void combine_k() {
    int bh = blockIdx.x;
    __shared__ float w[NSPLIT];
    __shared__ float invL;
    if (threadIdx.x == 0) {
        float M = -3e38f;
#pragma unroll
        for (int sp = 0; sp < NSPLIT; sp++) M = fmaxf(M, g_m[sp * (B * H) + bh]);
        float L = 0.f;
#pragma unroll
        for (int sp = 0; sp < NSPLIT; sp++) {
            float ww = __expf(g_m[sp * (B * H) + bh] - M);
            w[sp] = ww;
            L += ww * g_l[sp * (B * H) + bh];
        }
        invL = 1.f / L;
    }
    __syncthreads();
    for (int r = threadIdx.x; r < R; r += blockDim.x) {
        float acc = 0.f;
#pragma unroll
        for (int sp = 0; sp < NSPLIT; sp++)
            acc += w[sp] * g_ctxp[((size_t)sp * (B * H) + bh) * R + r];
        g_ctx[(size_t)bh * R + r] = acc * invL;
    }
}

// ---------------- vabsorb ----------------
__global__ void vabsorb_k(const float* __restrict__ w_vc) {
    const int h = blockIdx.y;
    const int ks = blockIdx.x;
    __shared__ float As[32][33];
    __shared__ float Bs[32][132];
    const int tid = threadIdx.x;
    const int ty = tid / 32, tx = tid % 32;
    float acc[4][4] = {};
    for (int r0 = ks * 128; r0 < ks * 128 + 128; r0 += 32) {
        {
            int r = tid / 8, c = (tid % 8) * 4;
            float4 v = *reinterpret_cast<const float4*>(g_ctx + (size_t)(r * H + h) * R + r0 + c);
            As[r][c] = v.x; As[r][c + 1] = v.y; As[r][c + 2] = v.z; As[r][c + 3] = v.w;
        }
#pragma unroll
        for (int it = 0; it < 4; it++) {
            int i = tid + it * 256;
            int rr = i / 32, c = (i % 32) * 4;
            float4 v = *reinterpret_cast<const float4*>(w_vc + (size_t)(h * R + r0 + rr) * D + c);
            *reinterpret_cast<float4*>(&Bs[rr][c]) = v;
        }
        __syncthreads();
#pragma unroll
        for (int dd = 0; dd < 32; dd++) {
            float4 bv = *reinterpret_cast<float4*>(&Bs[dd][tx * 4]);
            float bb[4] = {bv.x, bv.y, bv.z, bv.w};
#pragma unroll
            for (int i = 0; i < 4; i++) {
                float a = As[ty * 4 + i][dd];
#pragma unroll
                for (int j = 0; j < 4; j++) acc[i][j] += a * bb[j];
            }
        }
        __syncthreads();
    }
#pragma unroll
    for (int i = 0; i < 4; i++)
#pragma unroll
        for (int j = 0; j < 4; j++)
            g_part[(ks * B + ty * 4 + i) * HID + h * D + tx * 4 + j] = acc[i][j];
}

// ---------------- launch ----------------
extern "C" void kernel_launch(void* const* d_in, const int* in_sizes, int n_in,
                              void* d_out, int out_size) {
    const float* hs   = (const float*)d_in[0];
    const float* ckv  = (const float*)d_in[1];
    const float* q_w  = (const float*)d_in[2];
    const float* q_b  = (const float*)d_in[3];
    const float* w_kc = (const float*)d_in[4];
    const float* w_vc = (const float*)d_in[5];
    const float* o_w  = (const float*)d_in[6];
    const float* o_b  = (const float*)d_in[7];
    float* out = (float*)d_out;

    float *pq, *pattn;
    cudaGetSymbolAddress((void**)&pq, g_q);
    cudaGetSymbolAddress((void**)&pattn, g_attn);
    cudaFuncSetAttribute(fmla_k, cudaFuncAttributeMaxDynamicSharedMemorySize, SMEM_FMLA);
    cudaFuncSetAttribute(gemm_bf_k, cudaFuncAttributeMaxDynamicSharedMemorySize, SMEM_GEMM);

    gemm_bf_k<<<dim3(32, 8), 256, SMEM_GEMM>>>(hs, q_w);
    reduce8_k<<<512, 256>>>(pq, q_b);
    qabsorb_k<<<dim3(4, 32), 256>>>(w_kc);
    fmla_k<<<dim3(NSPLIT, B), 512, SMEM_FMLA>>>(ckv);
    combine_k<<<B * H, 128>>>();
    vabsorb_k<<<dim3(4, 32), 256>>>(w_vc);
    reduce4_k<<<512, 256>>>(pattn, nullptr);
    gemm_bf_k<<<dim3(32, 8), 256, SMEM_GEMM>>>(pattn, o_w);
    reduce8_k<<<512, 256>>>(out, o_b);
}

// round 17
// speedup vs baseline: 1.3018x; 1.0674x over previous
#include <cuda_runtime.h>
#include <cuda_bf16.h>
#include <cuda_fp16.h>
#include <cstdint>

#define B 32
#define H 32
#define D 128
#define R 512
#define S 4096
#define HID 4096
#define SCALE 0.08838834764831845f
#define NSPLIT 4
#define SB (S / NSPLIT)
#define SC 32
#define NCHUNK (SB / SC)

// ---------------- scratch ----------------
__device__ float g_q[B * HID];
__device__ float g_part[8 * B * HID];
__device__ float g_qa[B * H * R];
__device__ float g_ctx[B * H * R];
__device__ float g_attn[B * HID];
__device__ float g_ctxp[8 * B * H * R];
__device__ float g_m[8 * B * H];
__device__ float g_l[8 * B * H];

// ---------------- helpers ----------------
__device__ __forceinline__ uint32_t pack2(__nv_bfloat16 a, __nv_bfloat16 b) {
    return (uint32_t)__bfloat16_as_ushort(a) | ((uint32_t)__bfloat16_as_ushort(b) << 16);
}
__device__ __forceinline__ uint32_t pack2h(__half a, __half b) {
    return (uint32_t)__half_as_ushort(a) | ((uint32_t)__half_as_ushort(b) << 16);
}
// bf16 hi/lo split (projections)
__device__ __forceinline__ void split_store(float4 v, __nv_bfloat16* hp, __nv_bfloat16* lp) {
    __nv_bfloat16 h0 = __float2bfloat16(v.x), h1 = __float2bfloat16(v.y),
                  h2 = __float2bfloat16(v.z), h3 = __float2bfloat16(v.w);
    __nv_bfloat16 l0 = __float2bfloat16(v.x - __bfloat162float(h0));
    __nv_bfloat16 l1 = __float2bfloat16(v.y - __bfloat162float(h1));
    __nv_bfloat16 l2 = __float2bfloat16(v.z - __bfloat162float(h2));
    __nv_bfloat16 l3 = __float2bfloat16(v.w - __bfloat162float(h3));
    *reinterpret_cast<uint2*>(hp) = make_uint2(pack2(h0, h1), pack2(h2, h3));
    *reinterpret_cast<uint2*>(lp) = make_uint2(pack2(l0, l1), pack2(l2, l3));
}
// fp16 single store (A, V, in fmla)
__device__ __forceinline__ void store_h4(float4 v, __half* hp) {
    *reinterpret_cast<uint2*>(hp) = make_uint2(
        pack2h(__float2half(v.x), __float2half(v.y)),
        pack2h(__float2half(v.z), __float2half(v.w)));
}
__device__ __forceinline__ uint32_t saddr(const void* p) {
    return (uint32_t)__cvta_generic_to_shared(p);
}
__device__ __forceinline__ void ldsm4(uint32_t* r, const void* p) {
    asm volatile("ldmatrix.sync.aligned.m8n8.x4.shared.b16 {%0,%1,%2,%3},[%4];\n"
                 : "=r"(r[0]), "=r"(r[1]), "=r"(r[2]), "=r"(r[3]) : "r"(saddr(p)));
}
__device__ __forceinline__ void ldsm4t(uint32_t* r, const void* p) {
    asm volatile("ldmatrix.sync.aligned.m8n8.x4.trans.shared.b16 {%0,%1,%2,%3},[%4];\n"
                 : "=r"(r[0]), "=r"(r[1]), "=r"(r[2]), "=r"(r[3]) : "r"(saddr(p)));
}
// bf16 mma (projections)
__device__ __forceinline__ void mma16816(float* c, const uint32_t* a, uint32_t b0, uint32_t b1) {
    asm volatile(
        "mma.sync.aligned.m16n8k16.row.col.f32.bf16.bf16.f32 "
        "{%0,%1,%2,%3},{%4,%5,%6,%7},{%8,%9},{%0,%1,%2,%3};\n"
        : "+f"(c[0]), "+f"(c[1]), "+f"(c[2]), "+f"(c[3])
        : "r"(a[0]), "r"(a[1]), "r"(a[2]), "r"(a[3]), "r"(b0), "r"(b1));
}
// fp16 mma (fmla)
__device__ __forceinline__ void mma16816h(float* c, const uint32_t* a, uint32_t b0, uint32_t b1) {
    asm volatile(
        "mma.sync.aligned.m16n8k16.row.col.f32.f16.f16.f32 "
        "{%0,%1,%2,%3},{%4,%5,%6,%7},{%8,%9},{%0,%1,%2,%3};\n"
        : "+f"(c[0]), "+f"(c[1]), "+f"(c[2]), "+f"(c[3])
        : "r"(a[0]), "r"(a[1]), "r"(a[2]), "r"(a[3]), "r"(b0), "r"(b1));
}

// ---------------- bf16 hi/lo GEMM-NT, split-K 8, double-buffered smem
#define GA 2560
#define GW 10240
#define G_A0H 0
#define G_A0L (GA)
#define G_A1H (2*GA)
#define G_A1L (3*GA)
#define G_W0H (4*GA)
#define G_W0L (4*GA + GW)
#define G_W1H (4*GA + 2*GW)
#define G_W1L (4*GA + 3*GW)
#define SMEM_GEMM (4*GA + 4*GW)

__global__ void __launch_bounds__(256) gemm_bf_k(const float* __restrict__ A,
                                                 const float* __restrict__ W) {
    extern __shared__ char gsm[];
    const int n0 = blockIdx.x * 128;
    const int ks = blockIdx.y;
    const int tid = threadIdx.x;
    const int warp = tid >> 5, lane = tid & 31;
    const int g = lane >> 2, t = lane & 3;
    float c[2][2][4] = {};

    const int ar = tid >> 3, ac = (tid & 7) * 4;
    {
        int k0 = ks * 512;
        float4 va = *reinterpret_cast<const float4*>(A + ar * HID + k0 + ac);
        split_store(va, (__nv_bfloat16*)(gsm + G_A0H) + ar * 40 + ac,
                        (__nv_bfloat16*)(gsm + G_A0L) + ar * 40 + ac);
#pragma unroll
        for (int it = 0; it < 4; it++) {
            int i = it * 256 + tid;
            int r = i >> 3, cc = (i & 7) * 4;
            float4 v = *reinterpret_cast<const float4*>(W + (size_t)(n0 + r) * HID + k0 + cc);
            split_store(v, (__nv_bfloat16*)(gsm + G_W0H) + r * 40 + cc,
                           (__nv_bfloat16*)(gsm + G_W0L) + r * 40 + cc);
        }
    }
    __syncthreads();

    for (int it16 = 0; it16 < 16; it16++) {
        const char* curA_h = gsm + ((it16 & 1) ? G_A1H : G_A0H);
        const char* curA_l = gsm + ((it16 & 1) ? G_A1L : G_A0L);
        const char* curW_h = gsm + ((it16 & 1) ? G_W1H : G_W0H);
        const char* curW_l = gsm + ((it16 & 1) ? G_W1L : G_W0L);
        char* nxtA_h = gsm + ((it16 & 1) ? G_A0H : G_A1H);
        char* nxtA_l = gsm + ((it16 & 1) ? G_A0L : G_A1L);
        char* nxtW_h = gsm + ((it16 & 1) ? G_W0H : G_W1H);
        char* nxtW_l = gsm + ((it16 & 1) ? G_W0L : G_W1L);
        bool pf = (it16 + 1) < 16;
        float4 va, vw[4];
        if (pf) {
            int k0 = ks * 512 + (it16 + 1) * 32;
            va = *reinterpret_cast<const float4*>(A + ar * HID + k0 + ac);
#pragma unroll
            for (int itw = 0; itw < 4; itw++) {
                int i = itw * 256 + tid;
                vw[itw] = *reinterpret_cast<const float4*>(
                    W + (size_t)(n0 + (i >> 3)) * HID + k0 + ((i & 7) * 4));
            }
        }
#pragma unroll
        for (int kk = 0; kk < 2; kk++) {
            uint32_t ah[2][4], al[2][4];
#pragma unroll
            for (int mi = 0; mi < 2; mi++) {
                ldsm4(ah[mi], (const __nv_bfloat16*)curA_h + (mi * 16 + (lane & 15)) * 40 + kk * 16 + (lane >> 4) * 8);
                ldsm4(al[mi], (const __nv_bfloat16*)curA_l + (mi * 16 + (lane & 15)) * 40 + kk * 16 + (lane >> 4) * 8);
            }
            int brow = warp * 16 + ((lane >> 4) << 3) + (lane & 7);
            int bcol = kk * 16 + (((lane >> 3) & 1) << 3);
            uint32_t bh[4], bl[4];
            ldsm4(bh, (const __nv_bfloat16*)curW_h + brow * 40 + bcol);
            ldsm4(bl, (const __nv_bfloat16*)curW_l + brow * 40 + bcol);
#pragma unroll
            for (int nf = 0; nf < 2; nf++)
#pragma unroll
                for (int mi = 0; mi < 2; mi++)
                    mma16816(c[mi][nf], ah[mi], bh[nf * 2], bh[nf * 2 + 1]);
#pragma unroll
            for (int nf = 0; nf < 2; nf++)
#pragma unroll
                for (int mi = 0; mi < 2; mi++)
                    mma16816(c[mi][nf], ah[mi], bl[nf * 2], bl[nf * 2 + 1]);
#pragma unroll
            for (int nf = 0; nf < 2; nf++)
#pragma unroll
                for (int mi = 0; mi < 2; mi++)
                    mma16816(c[mi][nf], al[mi], bh[nf * 2], bh[nf * 2 + 1]);
        }
        if (pf) {
            split_store(va, (__nv_bfloat16*)nxtA_h + ar * 40 + ac,
                            (__nv_bfloat16*)nxtA_l + ar * 40 + ac);
#pragma unroll
            for (int itw = 0; itw < 4; itw++) {
                int i = itw * 256 + tid;
                int r = i >> 3, cc = (i & 7) * 4;
                split_store(vw[itw], (__nv_bfloat16*)nxtW_h + r * 40 + cc,
                                     (__nv_bfloat16*)nxtW_l + r * 40 + cc);
            }
        }
        __syncthreads();
    }
#pragma unroll
    for (int mi = 0; mi < 2; mi++)
#pragma unroll
        for (int nf = 0; nf < 2; nf++) {
            int row = mi * 16 + g;
            int col = n0 + warp * 16 + nf * 8 + 2 * t;
            float* o = g_part + ks * (B * HID) + (size_t)row * HID + col;
            *reinterpret_cast<float2*>(o) = make_float2(c[mi][nf][0], c[mi][nf][1]);
            *reinterpret_cast<float2*>(o + 8 * HID) = make_float2(c[mi][nf][2], c[mi][nf][3]);
        }
}

// ---------------- reduces
__global__ void reduce8_k(float* __restrict__ dst, const float* __restrict__ bias) {
    int i = blockIdx.x * 256 + threadIdx.x;
    float v = 0.f;
#pragma unroll
    for (int s = 0; s < 8; s++) v += g_part[s * 131072 + i];
    if (bias) v += bias[i & (HID - 1)];
    dst[i] = v;
}
__global__ void reduce4_k(float* __restrict__ dst, const float* __restrict__ bias) {
    int i = blockIdx.x * 256 + threadIdx.x;
    float v = g_part[i] + g_part[131072 + i] + g_part[2 * 131072 + i] + g_part[3 * 131072 + i];
    if (bias) v += bias[i & (HID - 1)];
    dst[i] = v;
}

// ---------------- q_absorbed
__global__ void qabsorb_k(const float* __restrict__ w_kc) {
    const int h = blockIdx.y;
    const int r0 = blockIdx.x * 128;
    __shared__ float As[32][33];
    __shared__ float Bs[32][132];
    const int tid = threadIdx.x;
    const int ty = tid / 32, tx = tid % 32;
    float acc[4][4] = {};
    for (int d0 = 0; d0 < 128; d0 += 32) {
        {
            int r = tid / 8, c = (tid % 8) * 4;
            float4 v = *reinterpret_cast<const float4*>(g_q + r * HID + h * D + d0 + c);
            As[r][c] = v.x; As[r][c + 1] = v.y; As[r][c + 2] = v.z; As[r][c + 3] = v.w;
        }
#pragma unroll
        for (int it = 0; it < 4; it++) {
            int i = tid + it * 256;
            int rr = i / 32, c = (i % 32) * 4;
            float4 v = *reinterpret_cast<const float4*>(w_kc + (size_t)(h * D + d0 + rr) * R + r0 + c);
            *reinterpret_cast<float4*>(&Bs[rr][c]) = v;
        }
        __syncthreads();
#pragma unroll
        for (int dd = 0; dd < 32; dd++) {
            float4 bv = *reinterpret_cast<float4*>(&Bs[dd][tx * 4]);
            float bb[4] = {bv.x, bv.y, bv.z, bv.w};
#pragma unroll
            for (int i = 0; i < 4; i++) {
                float a = As[ty * 4 + i][dd];
#pragma unroll
                for (int j = 0; j < 4; j++) acc[i][j] += a * bb[j];
            }
        }
        __syncthreads();
    }
#pragma unroll
    for (int i = 0; i < 4; i++)
#pragma unroll
        for (int j = 0; j < 4; j++)
            g_qa[((ty * 4 + i) * H + h) * R + r0 + tx * 4 + j] = acc[i][j];
}

// ---------------- fused flash MLA: full fp16 single-term, 512 threads, double-buffered V ----------------
// A (qa): fp16. V: fp16. P: fp16. QK = a*v (1 mma), PV = p*v (1 mma).
#define AST 520
#define PST 40
#define SRST 34
#define OFF_AH 0             /* 33280 */
#define OFF_V0 33280         /* 33280 */
#define OFF_V1 66560         /* 33280 */
#define OFF_PH 99840         /* 2560 */
#define OFF_SRED 102400      /* 3 x 32 x 34 floats = 13056 */
#define OFF_WMAX 115456      /* 64 floats */
#define OFF_WSUM 115712      /* 64 floats */
#define OFF_MROW 115968      /* 32 floats */
#define OFF_LROW 116096      /* 32 floats */
#define OFF_ALPHA 116224     /* 32 floats */
#define SMEM_FMLA 116352

__global__ void __launch_bounds__(512, 1) fmla_k(const float* __restrict__ ckv) {
    extern __shared__ char smbuf[];
    __half* Ah = reinterpret_cast<__half*>(smbuf + OFF_AH);
    __half* Ph = reinterpret_cast<__half*>(smbuf + OFF_PH);
    float* Sred = reinterpret_cast<float*>(smbuf + OFF_SRED);
    float* wmax = reinterpret_cast<float*>(smbuf + OFF_WMAX);
    float* wsum = reinterpret_cast<float*>(smbuf + OFF_WSUM);
    float* mrow = reinterpret_cast<float*>(smbuf + OFF_MROW);
    float* lrow = reinterpret_cast<float*>(smbuf + OFF_LROW);
    float* salpha = reinterpret_cast<float*>(smbuf + OFF_ALPHA);

    const int sp = blockIdx.x, b = blockIdx.y;
    const int tid = threadIdx.x;
    const int warp = tid >> 5, lane = tid & 31;
    const int g = lane >> 2, t = lane & 3;
    const int kw = warp >> 2;            // 4-way k split over r
    const int mw = (warp >> 1) & 1;      // m half (heads)
    const int nw = warp & 1;             // n half (s)

    // prologue: A (fp16) and V(0) (fp16)
#pragma unroll
    for (int it = 0; it < 8; it++) {
        int i = it * 512 + tid;
        int row = i >> 7, cc = (i & 127) * 4;
        float4 v = *reinterpret_cast<const float4*>(g_qa + (size_t)(b * H + row) * R + cc);
        store_h4(v, &Ah[row * AST + cc]);
    }
    {
        const float4* src4 = reinterpret_cast<const float4*>(ckv + ((size_t)b * S + sp * SB) * R);
        __half* Vh = reinterpret_cast<__half*>(smbuf + OFF_V0);
#pragma unroll
        for (int it = 0; it < 8; it++) {
            int i = it * 512 + tid;
            int row = i >> 7, cc = (i & 127) * 4;
            store_h4(src4[i], &Vh[row * AST + cc]);
        }
    }
    if (tid < 32) { mrow[tid] = -3e38f; lrow[tid] = 0.f; }
    __syncthreads();

    float cv[2][4][4] = {};

    for (int ch = 0; ch < NCHUNK; ch++) {
        const __half* Vc = reinterpret_cast<const __half*>(smbuf + ((ch & 1) ? OFF_V1 : OFF_V0));
        __half* Vn = reinterpret_cast<__half*>(smbuf + ((ch & 1) ? OFF_V0 : OFF_V1));
        const bool pf = (ch + 1) < NCHUNK;
        const float4* src4 = reinterpret_cast<const float4*>(
            ckv + ((size_t)b * S + sp * SB + (ch + 1) * SC) * R);

        float cq[2][4] = {};
        float4 pv[4];
        if (pf) {
#pragma unroll
            for (int j = 0; j < 4; j++) pv[j] = src4[j * 512 + tid];
        }
        // ---- QK part 1 (kk 0..3): single fp16 term ----
#pragma unroll
        for (int kk = 0; kk < 4; kk++) {
            int k0 = kw * 128 + kk * 16;
            uint32_t ah[4];
            ldsm4(ah, &Ah[(mw * 16 + (lane & 15)) * AST + k0 + (lane >> 4) * 8]);
            int brow = nw * 16 + ((lane >> 4) << 3) + (lane & 7);
            int bcol = k0 + (((lane >> 3) & 1) << 3);
            uint32_t bh[4];
            ldsm4(bh, &Vc[brow * AST + bcol]);
#pragma unroll
            for (int nf = 0; nf < 2; nf++) mma16816h(cq[nf], ah, bh[nf * 2], bh[nf * 2 + 1]);
        }
        if (pf) {
#pragma unroll
            for (int j = 0; j < 4; j++) {
                int i = j * 512 + tid;
                int row = i >> 7, cc = (i & 127) * 4;
                store_h4(pv[j], &Vn[row * AST + cc]);
            }
#pragma unroll
            for (int j = 0; j < 4; j++) pv[j] = src4[(j + 4) * 512 + tid];
        }
        // ---- QK part 2 (kk 4..7) ----
#pragma unroll
        for (int kk = 4; kk < 8; kk++) {
            int k0 = kw * 128 + kk * 16;
            uint32_t ah[4];
            ldsm4(ah, &Ah[(mw * 16 + (lane & 15)) * AST + k0 + (lane >> 4) * 8]);
            int brow = nw * 16 + ((lane >> 4) << 3) + (lane & 7);
            int bcol = k0 + (((lane >> 3) & 1) << 3);
            uint32_t bh[4];
            ldsm4(bh, &Vc[brow * AST + bcol]);
#pragma unroll
            for (int nf = 0; nf < 2; nf++) mma16816h(cq[nf], ah, bh[nf * 2], bh[nf * 2 + 1]);
        }
        if (pf) {
#pragma unroll
            for (int j = 0; j < 4; j++) {
                int i = (j + 4) * 512 + tid;
                int row = i >> 7, cc = (i & 127) * 4;
                store_h4(pv[j], &Vn[row * AST + cc]);
            }
        }
        // ---- k-split reduction + online softmax ----
        if (kw > 0) {
#pragma unroll
            for (int nf = 0; nf < 2; nf++) {
                int col = nw * 16 + nf * 8 + 2 * t;
                float* s0 = &Sred[(kw - 1) * 1088 + (mw * 16 + g) * SRST + col];
                *reinterpret_cast<float2*>(s0) = make_float2(cq[nf][0], cq[nf][1]);
                *reinterpret_cast<float2*>(s0 + 8 * SRST) = make_float2(cq[nf][2], cq[nf][3]);
            }
        }
        __syncthreads();
        if (kw == 0) {
            float mA = -3e38f, mB = -3e38f;
#pragma unroll
            for (int nf = 0; nf < 2; nf++) {
                int col = nw * 16 + nf * 8 + 2 * t;
#pragma unroll
                for (int p = 0; p < 3; p++) {
                    float2 r0 = *reinterpret_cast<float2*>(&Sred[p * 1088 + (mw * 16 + g) * SRST + col]);
                    float2 r1 = *reinterpret_cast<float2*>(&Sred[p * 1088 + (mw * 16 + g + 8) * SRST + col]);
                    cq[nf][0] += r0.x; cq[nf][1] += r0.y;
                    cq[nf][2] += r1.x; cq[nf][3] += r1.y;
                }
                cq[nf][0] *= SCALE; cq[nf][1] *= SCALE;
                cq[nf][2] *= SCALE; cq[nf][3] *= SCALE;
                mA = fmaxf(mA, fmaxf(cq[nf][0], cq[nf][1]));
                mB = fmaxf(mB, fmaxf(cq[nf][2], cq[nf][3]));
            }
            mA = fmaxf(mA, __shfl_xor_sync(0xffffffffu, mA, 1));
            mA = fmaxf(mA, __shfl_xor_sync(0xffffffffu, mA, 2));
            mB = fmaxf(mB, __shfl_xor_sync(0xffffffffu, mB, 1));
            mB = fmaxf(mB, __shfl_xor_sync(0xffffffffu, mB, 2));
            if (t == 0) {
                wmax[nw * 32 + mw * 16 + g] = mA;
                wmax[nw * 32 + mw * 16 + g + 8] = mB;
            }
        }
        __syncthreads();
        if (tid < 32) {
            float cm = fmaxf(wmax[tid], wmax[32 + tid]);
            float mo = mrow[tid];
            float mn = fmaxf(mo, cm);
            salpha[tid] = __expf(mo - mn);
            mrow[tid] = mn;
        }
        __syncthreads();
        {
#pragma unroll
            for (int mi = 0; mi < 2; mi++) {
                float rA = salpha[mi * 16 + g], rB = salpha[mi * 16 + g + 8];
#pragma unroll
                for (int nj = 0; nj < 4; nj++) {
                    cv[mi][nj][0] *= rA; cv[mi][nj][1] *= rA;
                    cv[mi][nj][2] *= rB; cv[mi][nj][3] *= rB;
                }
            }
        }
        if (kw == 0) {
            int rA = mw * 16 + g;
            float mA = mrow[rA], mB = mrow[rA + 8];
            float sA = 0.f, sB = 0.f;
#pragma unroll
            for (int nf = 0; nf < 2; nf++) {
                float p0 = __expf(cq[nf][0] - mA), p1 = __expf(cq[nf][1] - mA);
                float p2 = __expf(cq[nf][2] - mB), p3 = __expf(cq[nf][3] - mB);
                sA += p0 + p1; sB += p2 + p3;
                int col = nw * 16 + nf * 8 + 2 * t;
                *reinterpret_cast<uint32_t*>(&Ph[rA * PST + col]) =
                    pack2h(__float2half(p0), __float2half(p1));
                *reinterpret_cast<uint32_t*>(&Ph[(rA + 8) * PST + col]) =
                    pack2h(__float2half(p2), __float2half(p3));
            }
            sA += __shfl_xor_sync(0xffffffffu, sA, 1);
            sA += __shfl_xor_sync(0xffffffffu, sA, 2);
            sB += __shfl_xor_sync(0xffffffffu, sB, 1);
            sB += __shfl_xor_sync(0xffffffffu, sB, 2);
            if (t == 0) { wsum[nw * 32 + rA] = sA; wsum[nw * 32 + rA + 8] = sB; }
        }
        __syncthreads();
        if (tid < 32) lrow[tid] = lrow[tid] * salpha[tid] + wsum[tid] + wsum[32 + tid];

        // ---- PV: ctx(32 x warp-n32) += P(32x32) @ V(32x512), single fp16 term ----
#pragma unroll
        for (int kk = 0; kk < 2; kk++) {
            int k0 = kk * 16;
            uint32_t ph[2][4];
#pragma unroll
            for (int mi = 0; mi < 2; mi++)
                ldsm4(ph[mi], &Ph[(mi * 16 + (lane & 15)) * PST + k0 + (lane >> 4) * 8]);
#pragma unroll
            for (int j2 = 0; j2 < 2; j2++) {
                int vrow = k0 + (lane & 7) + (((lane >> 3) & 1) << 3);
                int vcol = warp * 32 + j2 * 16 + (lane >> 4) * 8;
                uint32_t vh[4];
                ldsm4t(vh, &Vc[vrow * AST + vcol]);
#pragma unroll
                for (int half = 0; half < 2; half++)
#pragma unroll
                    for (int mi = 0; mi < 2; mi++)
                        mma16816h(cv[mi][j2 * 2 + half], ph[mi], vh[half * 2], vh[half * 2 + 1]);
            }
        }
        __syncthreads();
    }
    if (tid < 32) {
        g_m[(sp * B + b) * H + tid] = mrow[tid];
        g_l[(sp * B + b) * H + tid] = lrow[tid];
    }
#pragma unroll
    for (int mi = 0; mi < 2; mi++)
#pragma unroll
        for (int nj = 0; nj < 4; nj++) {
            int row = mi * 16 + g;
            int col = warp * 32 + nj * 8 + 2 * t;
            float* o = g_ctxp + ((size_t)(sp * B + b) * H + row) * R + col;
            *reinterpret_cast<float2*>(o) = make_float2(cv[mi][nj][0], cv[mi][nj][1]);
            *reinterpret_cast<float2*>(o + 8 * R) = make_float2(cv[mi][nj][2], cv[mi][nj][3]);
        }
}

// ---------------- combine ----------------
__global__ void combine_k() {
    int bh = blockIdx.x;
    __shared__ float w[NSPLIT];
    __shared__ float invL;
    if (threadIdx.x == 0) {
        float M = -3e38f;
#pragma unroll
        for (int sp = 0; sp < NSPLIT; sp++) M = fmaxf(M, g_m[sp * (B * H) + bh]);
        float L = 0.f;
#pragma unroll
        for (int sp = 0; sp < NSPLIT; sp++) {
            float ww = __expf(g_m[sp * (B * H) + bh] - M);
            w[sp] = ww;
            L += ww * g_l[sp * (B * H) + bh];
        }
        invL = 1.f / L;
    }
    __syncthreads();
    for (int r = threadIdx.x; r < R; r += blockDim.x) {
        float acc = 0.f;
#pragma unroll
        for (int sp = 0; sp < NSPLIT; sp++)
            acc += w[sp] * g_ctxp[((size_t)sp * (B * H) + bh) * R + r];
        g_ctx[(size_t)bh * R + r] = acc * invL;
    }
}

// ---------------- vabsorb ----------------
__global__ void vabsorb_k(const float* __restrict__ w_vc) {
    const int h = blockIdx.y;
    const int ks = blockIdx.x;
    __shared__ float As[32][33];
    __shared__ float Bs[32][132];
    const int tid = threadIdx.x;
    const int ty = tid / 32, tx = tid % 32;
    float acc[4][4] = {};
    for (int r0 = ks * 128; r0 < ks * 128 + 128; r0 += 32) {
        {
            int r = tid / 8, c = (tid % 8) * 4;
            float4 v = *reinterpret_cast<const float4*>(g_ctx + (size_t)(r * H + h) * R + r0 + c);
            As[r][c] = v.x; As[r][c + 1] = v.y; As[r][c + 2] = v.z; As[r][c + 3] = v.w;
        }
#pragma unroll
        for (int it = 0; it < 4; it++) {
            int i = tid + it * 256;
            int rr = i / 32, c = (i % 32) * 4;
            float4 v = *reinterpret_cast<const float4*>(w_vc + (size_t)(h * R + r0 + rr) * D + c);
            *reinterpret_cast<float4*>(&Bs[rr][c]) = v;
        }
        __syncthreads();
#pragma unroll
        for (int dd = 0; dd < 32; dd++) {
            float4 bv = *reinterpret_cast<float4*>(&Bs[dd][tx * 4]);
            float bb[4] = {bv.x, bv.y, bv.z, bv.w};
#pragma unroll
            for (int i = 0; i < 4; i++) {
                float a = As[ty * 4 + i][dd];
#pragma unroll
                for (int j = 0; j < 4; j++) acc[i][j] += a * bb[j];
            }
        }
        __syncthreads();
    }
#pragma unroll
    for (int i = 0; i < 4; i++)
#pragma unroll
        for (int j = 0; j < 4; j++)
            g_part[(ks * B + ty * 4 + i) * HID + h * D + tx * 4 + j] = acc[i][j];
}

// ---------------- launch ----------------
extern "C" void kernel_launch(void* const* d_in, const int* in_sizes, int n_in,
                              void* d_out, int out_size) {
    const float* hs   = (const float*)d_in[0];
    const float* ckv  = (const float*)d_in[1];
    const float* q_w  = (const float*)d_in[2];
    const float* q_b  = (const float*)d_in[3];
    const float* w_kc = (const float*)d_in[4];
    const float* w_vc = (const float*)d_in[5];
    const float* o_w  = (const float*)d_in[6];
    const float* o_b  = (const float*)d_in[7];
    float* out = (float*)d_out;

    float *pq, *pattn;
    cudaGetSymbolAddress((void**)&pq, g_q);
    cudaGetSymbolAddress((void**)&pattn, g_attn);
    cudaFuncSetAttribute(fmla_k, cudaFuncAttributeMaxDynamicSharedMemorySize, SMEM_FMLA);
    cudaFuncSetAttribute(gemm_bf_k, cudaFuncAttributeMaxDynamicSharedMemorySize, SMEM_GEMM);

    gemm_bf_k<<<dim3(32, 8), 256, SMEM_GEMM>>>(hs, q_w);
    reduce8_k<<<512, 256>>>(pq, q_b);
    qabsorb_k<<<dim3(4, 32), 256>>>(w_kc);
    fmla_k<<<dim3(NSPLIT, B), 512, SMEM_FMLA>>>(ckv);
    combine_k<<<B * H, 128>>>();
    vabsorb_k<<<dim3(4, 32), 256>>>(w_vc);
    reduce4_k<<<512, 256>>>(pattn, nullptr);
    gemm_bf_k<<<dim3(32, 8), 256, SMEM_GEMM>>>(pattn, o_w);
    reduce8_k<<<512, 256>>>(out, o_b);
}